// round 15
// baseline (speedup 1.0000x reference)
#include <cuda_runtime.h>
#include <cfloat>
#include <cstddef>

#define NB 64   // batch

typedef unsigned long long u64;

// ---- packed f32x2 helpers ---------------------------------------------------
__device__ __forceinline__ u64 pk2(float lo, float hi){
  u64 r; asm("mov.b64 %0,{%1,%2};" : "=l"(r) : "f"(lo), "f"(hi)); return r;
}
__device__ __forceinline__ float2 up2(u64 v){
  float2 f; asm("mov.b64 {%0,%1},%2;" : "=f"(f.x), "=f"(f.y) : "l"(v)); return f;
}
__device__ __forceinline__ void fma2(u64 &d, u64 a, u64 b){
  asm("fma.rn.f32x2 %0,%1,%2,%0;" : "+l"(d) : "l"(a), "l"(b));
}

// ---------------- scratch buffers (device globals; no allocations) ----------
__device__ __align__(16) float g_A1[(size_t)NB*64*64*64];   // enc conv1 out
__device__ __align__(16) float g_A2[(size_t)NB*128*32*32];  // enc conv2 out
__device__ __align__(16) float g_A3[(size_t)NB*128*32*32];  // enc conv3/res
__device__ __align__(16) float g_T [(size_t)NB*32*32*32];   // res 3x3 temp
__device__ __align__(16) float g_Z [(size_t)NB*32*32*64];   // z NHWC
__device__ __align__(16) float g_ZQ[(size_t)NB*64*32*32];   // z_q NCHW
__device__ __align__(16) float g_D1[(size_t)NB*128*32*32];  // dec trunk
__device__ __align__(16) float g_U1[(size_t)NB*64*64*64];   // dec upsample
// pre-transposed weights: [ci][tap][co]
__device__ __align__(16) float g_TW_E1[3*16*64];
__device__ __align__(16) float g_TW_E2[64*16*128];
__device__ __align__(16) float g_TW_E3[128*9*128];
__device__ __align__(16) float g_TW_R1A[128*9*32];
__device__ __align__(16) float g_TW_R2A[128*9*32];
__device__ __align__(16) float g_TW_DR1A[128*9*32];
__device__ __align__(16) float g_TW_DR2A[128*9*32];
__device__ __align__(16) float g_TW_DEC[64*9*128];          // flipped dw1
__device__ __align__(16) float g_TW_D2[128*16*64];
__device__ __align__(16) float g_TW_D3[64*16*4];            // co padded 3->4
__device__ float  g_ESQ[1024];
__device__ int    g_IDX[65536];
__device__ double g_PART[512];

__device__ __forceinline__ float* gbuf(int id){
  switch(id){
    case 0: return g_A1; case 1: return g_A2; case 2: return g_A3;
    case 3: return g_T;  case 4: return g_Z;  case 5: return g_ZQ;
    case 6: return g_D1; case 7: return g_U1;
    case 10: return g_TW_E1;  case 11: return g_TW_E2;  case 12: return g_TW_E3;
    case 13: return g_TW_R1A; case 14: return g_TW_R2A; case 15: return g_TW_DR1A;
    case 16: return g_TW_DR2A;case 17: return g_TW_DEC; case 18: return g_TW_D2;
    default: return g_TW_D3;
  }
}
__device__ __forceinline__ const float* gbuf_c(int id, const float* ext){
  if (id < 0) return ext;
  return gbuf(id);
}

// ---------------- merged prep: esq + all weight transposes -------------------
__device__ __forceinline__ void trA_i(const float* __restrict__ w, float* T,
                                      int CI,int CO,int KK,int t){
  int co = t/(CI*KK); int r = t%(CI*KK); int ci = r/KK, kk = r%KK;
  T[((size_t)ci*KK+kk)*CO+co] = w[t];
}
__device__ __forceinline__ void trB_i(const float* __restrict__ w, float* T,
                                      int CI,int CO,int KK,int COP,int t){
  int ci = t/(CO*KK); int r = t%(CO*KK); int co = r/KK, kk = r%KK;
  T[((size_t)ci*KK+kk)*COP+co] = w[t];
}

__global__ void k_prep(const float* __restrict__ emb,
                       const float* __restrict__ ew1, const float* __restrict__ ew2,
                       const float* __restrict__ ew3,
                       const float* __restrict__ er1a, const float* __restrict__ er2a,
                       const float* __restrict__ dr1a, const float* __restrict__ dr2a,
                       const float* __restrict__ dw1, const float* __restrict__ dw2,
                       const float* __restrict__ dw3)
{
  int t = blockIdx.x*256 + threadIdx.x;
  if (t < 1024){
    const float4* e = reinterpret_cast<const float4*>(emb + (size_t)t*64);
    float s = 0.f;
    #pragma unroll
    for (int i=0;i<16;i++){
      float4 v = e[i];
      s = fmaf(v.x,v.x,fmaf(v.y,v.y,fmaf(v.z,v.z,fmaf(v.w,v.w,s))));
    }
    g_ESQ[t] = s; return;
  } t -= 1024;
  if (t < 3072){ trA_i(ew1, g_TW_E1, 3,64,16, t); return; } t -= 3072;
  if (t < 131072){ trA_i(ew2, g_TW_E2, 64,128,16, t); return; } t -= 131072;
  if (t < 147456){ trA_i(ew3, g_TW_E3, 128,128,9, t); return; } t -= 147456;
  if (t < 36864){ trA_i(er1a, g_TW_R1A, 128,32,9, t); return; } t -= 36864;
  if (t < 36864){ trA_i(er2a, g_TW_R2A, 128,32,9, t); return; } t -= 36864;
  if (t < 36864){ trA_i(dr1a, g_TW_DR1A, 128,32,9, t); return; } t -= 36864;
  if (t < 36864){ trA_i(dr2a, g_TW_DR2A, 128,32,9, t); return; } t -= 36864;
  if (t < 73728){
    int ci = t/(128*9); int r = t%(128*9); int co = r/9, kk = r%9;
    int ky = kk/3, kx = kk%3;
    g_TW_DEC[((size_t)ci*9 + (2-ky)*3 + (2-kx))*128 + co] = dw1[t]; return;
  } t -= 73728;
  if (t < 131072){ trB_i(dw2, g_TW_D2, 128,64,16,64, t); return; } t -= 131072;
  if (t < 3072){ trB_i(dw3, g_TW_D3, 64,3,16,4, t); }
}

// ---------------- 3x3 s1 p1 conv at 32x32, f32x2, DUAL-IMAGE, 2-ci stages ----
template<int CIN,int COUT,int COT,bool RIN,bool ROUT,bool HASB>
__global__ void __launch_bounds__(256,2)
k_conv3d(int in_id, int w_id, const float* __restrict__ bias, int out_id)
{
  constexpr int CP   = COT/2;
  constexpr int WSZ  = 9*COT;
  constexpr int WTOT = 2*WSZ;
  static_assert(WTOT <= 256, "weight staging assumes one element per thread");
  static_assert(CIN % 2 == 0, "paired ci staging");
  __shared__ __align__(16) float sIn[2][2][2][34*40];   // buf, img, plane
  __shared__ __align__(16) float sW [2][WTOT];
  const float* in = gbuf_c(in_id, nullptr);
  const float* W  = gbuf_c(w_id, nullptr);
  float* out = gbuf(out_id);
  int co0 = blockIdx.x*COT;
  int b0  = blockIdx.y*2;
  int tid = threadIdx.x;
  int tx = tid & 7, ty = tid >> 3;
  int x0 = tx*4;

  for (int i=tid; i<34*40; i+=256){
    sIn[0][0][0][i]=0.f; sIn[0][0][1][i]=0.f; sIn[0][1][0][i]=0.f; sIn[0][1][1][i]=0.f;
    sIn[1][0][0][i]=0.f; sIn[1][0][1][i]=0.f; sIn[1][1][0][i]=0.f; sIn[1][1][1][i]=0.f;
  }
  __syncthreads();

  u64 acc0[CP][4], acc1[CP][4];
  #pragma unroll
  for (int j=0;j<CP;j++){
    u64 bp = HASB ? pk2(__ldg(bias+co0+2*j), __ldg(bias+co0+2*j+1)) : 0ull;
    #pragma unroll
    for (int p=0;p<4;p++){ acc0[j][p] = bp; acc1[j][p] = bp; }
  }

  const float* ip0 = in + (size_t)b0*CIN*1024;
  const float* ip1 = ip0 + (size_t)CIN*1024;
  bool wact = tid < WTOT;
  int wpl = tid / WSZ, wrem = tid % WSZ;
  int wtap = wrem / COT, wco = wrem % COT;
  const float* wbase = W + ((size_t)wpl*9 + wtap)*COUT + co0 + wco;

  float4 i0a = __ldg(reinterpret_cast<const float4*>(ip0) + tid);
  float4 i0c = __ldg(reinterpret_cast<const float4*>(ip0 + 1024) + tid);
  float4 i1a = __ldg(reinterpret_cast<const float4*>(ip1) + tid);
  float4 i1c = __ldg(reinterpret_cast<const float4*>(ip1 + 1024) + tid);
  if (RIN){
    i0a.x=fmaxf(i0a.x,0.f); i0a.y=fmaxf(i0a.y,0.f); i0a.z=fmaxf(i0a.z,0.f); i0a.w=fmaxf(i0a.w,0.f);
    i0c.x=fmaxf(i0c.x,0.f); i0c.y=fmaxf(i0c.y,0.f); i0c.z=fmaxf(i0c.z,0.f); i0c.w=fmaxf(i0c.w,0.f);
    i1a.x=fmaxf(i1a.x,0.f); i1a.y=fmaxf(i1a.y,0.f); i1a.z=fmaxf(i1a.z,0.f); i1a.w=fmaxf(i1a.w,0.f);
    i1c.x=fmaxf(i1c.x,0.f); i1c.y=fmaxf(i1c.y,0.f); i1c.z=fmaxf(i1c.z,0.f); i1c.w=fmaxf(i1c.w,0.f);
  }
  float wv0 = wact ? __ldg(wbase) : 0.f;

  int sbase = (ty+1)*40 + 1 + x0;
  int pb = 0;
  for (int ci=0; ci<CIN; ci+=2){
    { float* sp = &sIn[pb][0][0][sbase]; sp[0]=i0a.x; sp[1]=i0a.y; sp[2]=i0a.z; sp[3]=i0a.w; }
    { float* sp = &sIn[pb][0][1][sbase]; sp[0]=i0c.x; sp[1]=i0c.y; sp[2]=i0c.z; sp[3]=i0c.w; }
    { float* sp = &sIn[pb][1][0][sbase]; sp[0]=i1a.x; sp[1]=i1a.y; sp[2]=i1a.z; sp[3]=i1a.w; }
    { float* sp = &sIn[pb][1][1][sbase]; sp[0]=i1c.x; sp[1]=i1c.y; sp[2]=i1c.z; sp[3]=i1c.w; }
    if (wact) sW[pb][tid] = wv0;
    __syncthreads();
    if (ci+2 < CIN){
      i0a = __ldg(reinterpret_cast<const float4*>(ip0 + (size_t)(ci+2)*1024) + tid);
      i0c = __ldg(reinterpret_cast<const float4*>(ip0 + (size_t)(ci+3)*1024) + tid);
      i1a = __ldg(reinterpret_cast<const float4*>(ip1 + (size_t)(ci+2)*1024) + tid);
      i1c = __ldg(reinterpret_cast<const float4*>(ip1 + (size_t)(ci+3)*1024) + tid);
      if (RIN){
        i0a.x=fmaxf(i0a.x,0.f); i0a.y=fmaxf(i0a.y,0.f); i0a.z=fmaxf(i0a.z,0.f); i0a.w=fmaxf(i0a.w,0.f);
        i0c.x=fmaxf(i0c.x,0.f); i0c.y=fmaxf(i0c.y,0.f); i0c.z=fmaxf(i0c.z,0.f); i0c.w=fmaxf(i0c.w,0.f);
        i1a.x=fmaxf(i1a.x,0.f); i1a.y=fmaxf(i1a.y,0.f); i1a.z=fmaxf(i1a.z,0.f); i1a.w=fmaxf(i1a.w,0.f);
        i1c.x=fmaxf(i1c.x,0.f); i1c.y=fmaxf(i1c.y,0.f); i1c.z=fmaxf(i1c.z,0.f); i1c.w=fmaxf(i1c.w,0.f);
      }
      if (wact) wv0 = __ldg(wbase + (size_t)(ci+2)*9*COUT);
    }
    #pragma unroll
    for (int pl=0; pl<2; pl++){
      #pragma unroll
      for (int ky=0;ky<3;ky++){
        const float* r0 = &sIn[pb][0][pl][(ty+ky)*40 + x0];
        const float* r1 = &sIn[pb][1][pl][(ty+ky)*40 + x0];
        float4 a0 = *reinterpret_cast<const float4*>(r0);
        float2 e0 = *reinterpret_cast<const float2*>(r0+4);
        float4 a1 = *reinterpret_cast<const float4*>(r1);
        float2 e1 = *reinterpret_cast<const float2*>(r1+4);
        u64 vb0[6], vb1[6];
        vb0[0]=pk2(a0.x,a0.x); vb0[1]=pk2(a0.y,a0.y); vb0[2]=pk2(a0.z,a0.z);
        vb0[3]=pk2(a0.w,a0.w); vb0[4]=pk2(e0.x,e0.x); vb0[5]=pk2(e0.y,e0.y);
        vb1[0]=pk2(a1.x,a1.x); vb1[1]=pk2(a1.y,a1.y); vb1[2]=pk2(a1.z,a1.z);
        vb1[3]=pk2(a1.w,a1.w); vb1[4]=pk2(e1.x,e1.x); vb1[5]=pk2(e1.y,e1.y);
        #pragma unroll
        for (int kx=0;kx<3;kx++){
          const ulonglong2* wq = reinterpret_cast<const ulonglong2*>(&sW[pb][pl*WSZ + (ky*3+kx)*COT]);
          #pragma unroll
          for (int j2=0;j2<CP/2;j2++){
            ulonglong2 wv = wq[j2];
            #pragma unroll
            for (int p=0;p<4;p++){
              fma2(acc0[2*j2  ][p], wv.x, vb0[kx+p]);
              fma2(acc0[2*j2+1][p], wv.y, vb0[kx+p]);
              fma2(acc1[2*j2  ][p], wv.x, vb1[kx+p]);
              fma2(acc1[2*j2+1][p], wv.y, vb1[kx+p]);
            }
          }
        }
      }
    }
    pb ^= 1;
  }
  #pragma unroll
  for (int j=0;j<CP;j++){
    float2 f0=up2(acc0[j][0]), f1=up2(acc0[j][1]), f2=up2(acc0[j][2]), f3=up2(acc0[j][3]);
    float4 oe = make_float4(f0.x,f1.x,f2.x,f3.x);
    float4 oo = make_float4(f0.y,f1.y,f2.y,f3.y);
    if (ROUT){
      oe.x=fmaxf(oe.x,0.f); oe.y=fmaxf(oe.y,0.f); oe.z=fmaxf(oe.z,0.f); oe.w=fmaxf(oe.w,0.f);
      oo.x=fmaxf(oo.x,0.f); oo.y=fmaxf(oo.y,0.f); oo.z=fmaxf(oo.z,0.f); oo.w=fmaxf(oo.w,0.f);
    }
    *reinterpret_cast<float4*>(out + ((size_t)(b0*COUT+co0+2*j  )*32 + ty)*32 + x0) = oe;
    *reinterpret_cast<float4*>(out + ((size_t)(b0*COUT+co0+2*j+1)*32 + ty)*32 + x0) = oo;
    float2 g0=up2(acc1[j][0]), g1=up2(acc1[j][1]), g2=up2(acc1[j][2]), g3=up2(acc1[j][3]);
    float4 pe = make_float4(g0.x,g1.x,g2.x,g3.x);
    float4 po = make_float4(g0.y,g1.y,g2.y,g3.y);
    if (ROUT){
      pe.x=fmaxf(pe.x,0.f); pe.y=fmaxf(pe.y,0.f); pe.z=fmaxf(pe.z,0.f); pe.w=fmaxf(pe.w,0.f);
      po.x=fmaxf(po.x,0.f); po.y=fmaxf(po.y,0.f); po.z=fmaxf(po.z,0.f); po.w=fmaxf(po.w,0.f);
    }
    *reinterpret_cast<float4*>(out + ((size_t)((b0+1)*COUT+co0+2*j  )*32 + ty)*32 + x0) = pe;
    *reinterpret_cast<float4*>(out + ((size_t)((b0+1)*COUT+co0+2*j+1)*32 + ty)*32 + x0) = po;
  }
}

// ---------------- 4x4 s2 p1 conv, f32x2, dbl-buf input+weights ---------------
template<int CIN,int COUT,int HIN,int COT>
__global__ void __launch_bounds__(256,2)
k_conv4s(const float* __restrict__ ext_in, int in_id, int w_id,
         const float* __restrict__ bias, int out_id)
{
  constexpr int CP = COT/2;
  constexpr int HOUT = HIN/2;
  constexpr int XT   = HOUT/32;
  constexpr int WSZ  = 16*COT;
  static_assert(WSZ <= 256, "weight staging assumes one element per thread");
  __shared__ __align__(16) float sIn[2][66*72];
  __shared__ __align__(16) float sW [2][WSZ];
  const float* in = gbuf_c(in_id, ext_in);
  const float* W  = gbuf_c(w_id, nullptr);
  float* out = gbuf(out_id);
  int co0 = blockIdx.x*COT;
  int oy0 = (blockIdx.y/XT)*32, ox0 = (blockIdx.y%XT)*32;
  int b = blockIdx.z;
  int tid = threadIdx.x;
  int tx = tid & 7, ty = tid >> 3;
  int x0 = tx*4;

  u64 acc[CP][4];
  #pragma unroll
  for (int j=0;j<CP;j++){
    u64 bp = pk2(__ldg(bias+co0+2*j), __ldg(bias+co0+2*j+1));
    #pragma unroll
    for (int p=0;p<4;p++) acc[j][p] = bp;
  }

  int iy0 = oy0*2 - 1, ix0 = ox0*2 - 1;
  int wk = tid / COT, wj = tid % COT;
  bool wact = tid < WSZ;
  const float* wsrc0 = W + (size_t)wk*COUT + co0 + wj;

  float sreg[18];
  {
    const float* ip = in + (size_t)b*CIN*HIN*HIN;
    #pragma unroll
    for (int t=0;t<18;t++){
      int s = tid + t*256; float v = 0.f;
      if (s < 4356){
        int r = s/66, c = s - r*66;
        int giy = iy0 + r, gix = ix0 + c;
        if (giy>=0 && giy<HIN && gix>=0 && gix<HIN) v = __ldg(ip + (size_t)giy*HIN + gix);
      }
      sreg[t] = v;
    }
  }
  float wv0 = wact ? __ldg(wsrc0) : 0.f;

  int pb = 0;
  for (int ci=0; ci<CIN; ci++){
    #pragma unroll
    for (int t=0;t<18;t++){
      int s = tid + t*256;
      if (s < 4356){ int r = s/66, c = s - r*66; sIn[pb][r*72 + c] = sreg[t]; }
    }
    if (wact) sW[pb][tid] = wv0;
    __syncthreads();
    if (ci+1 < CIN){
      const float* ip = in + (size_t)(b*CIN+ci+1)*HIN*HIN;
      #pragma unroll
      for (int t=0;t<18;t++){
        int s = tid + t*256; float v = 0.f;
        if (s < 4356){
          int r = s/66, c = s - r*66;
          int giy = iy0 + r, gix = ix0 + c;
          if (giy>=0 && giy<HIN && gix>=0 && gix<HIN) v = __ldg(ip + (size_t)giy*HIN + gix);
        }
        sreg[t] = v;
      }
      if (wact) wv0 = __ldg(wsrc0 + (size_t)(ci+1)*16*COUT);
    }
    #pragma unroll
    for (int ky=0;ky<4;ky++){
      const float* row = &sIn[pb][(2*ty+ky)*72 + 2*x0];
      float4 a  = *reinterpret_cast<const float4*>(row);
      float4 bq = *reinterpret_cast<const float4*>(row+4);
      float2 e89 = *reinterpret_cast<const float2*>(row+8);
      u64 vb[10];
      vb[0]=pk2(a.x,a.x); vb[1]=pk2(a.y,a.y); vb[2]=pk2(a.z,a.z); vb[3]=pk2(a.w,a.w);
      vb[4]=pk2(bq.x,bq.x); vb[5]=pk2(bq.y,bq.y); vb[6]=pk2(bq.z,bq.z); vb[7]=pk2(bq.w,bq.w);
      vb[8]=pk2(e89.x,e89.x); vb[9]=pk2(e89.y,e89.y);
      #pragma unroll
      for (int kx=0;kx<4;kx++){
        const ulonglong2* wq = reinterpret_cast<const ulonglong2*>(&sW[pb][(ky*4+kx)*COT]);
        #pragma unroll
        for (int j2=0;j2<CP/2;j2++){
          ulonglong2 wv = wq[j2];
          #pragma unroll
          for (int p=0;p<4;p++){
            fma2(acc[2*j2  ][p], wv.x, vb[kx+2*p]);
            fma2(acc[2*j2+1][p], wv.y, vb[kx+2*p]);
          }
        }
      }
    }
    pb ^= 1;
  }
  #pragma unroll
  for (int j=0;j<CP;j++){
    float2 f0=up2(acc[j][0]), f1=up2(acc[j][1]), f2=up2(acc[j][2]), f3=up2(acc[j][3]);
    float4 oe = make_float4(fmaxf(f0.x,0.f),fmaxf(f1.x,0.f),fmaxf(f2.x,0.f),fmaxf(f3.x,0.f));
    float4 oo = make_float4(fmaxf(f0.y,0.f),fmaxf(f1.y,0.f),fmaxf(f2.y,0.f),fmaxf(f3.y,0.f));
    *reinterpret_cast<float4*>(out + ((size_t)(b*COUT+co0+2*j  )*HOUT + oy0+ty)*HOUT + ox0+x0) = oe;
    *reinterpret_cast<float4*>(out + ((size_t)(b*COUT+co0+2*j+1)*HOUT + oy0+ty)*HOUT + ox0+x0) = oo;
  }
}

// ---------------- 1x1 conv residual-add, smem weights, input read once -------
__global__ void __launch_bounds__(256)
k_res1x1v(int t_id, const float* __restrict__ w, int x_id)
{
  __shared__ float sw[128*32];
  const float* t = gbuf_c(t_id, nullptr);
  float* x = gbuf(x_id);
  int b = blockIdx.y, p = blockIdx.x*256 + threadIdx.x;
  for (int i=threadIdx.x; i<4096; i+=256) sw[i] = __ldg(w+i);
  __syncthreads();
  float rv[32];
  #pragma unroll
  for (int ci=0;ci<32;ci++) rv[ci] = __ldg(t + (size_t)(b*32+ci)*1024 + p);
  #pragma unroll 4
  for (int co=0;co<128;co++){
    float a = 0.f;
    const float* wr = &sw[co*32];
    #pragma unroll
    for (int ci=0;ci<32;ci++) a = fmaf(wr[ci], rv[ci], a);
    x[(size_t)(b*128+co)*1024 + p] += a;
  }
}

// ---------------- pre-quant 1x1: relu(in) -> z NHWC, smem weights ------------
__global__ void __launch_bounds__(256)
k_pqv(int in_id, const float* __restrict__ w, const float* __restrict__ bias)
{
  __shared__ float swT[128*64];
  const float* h = gbuf_c(in_id, nullptr);
  int b = blockIdx.y, p = blockIdx.x*256 + threadIdx.x;
  for (int i=threadIdx.x; i<8192; i+=256){
    int d = i >> 7, ci = i & 127;
    swT[ci*64 + d] = __ldg(w + i);
  }
  __syncthreads();
  float acc[64];
  #pragma unroll
  for (int d=0;d<64;d++) acc[d] = __ldg(bias+d);
  const float* ip = h + (size_t)b*128*1024 + p;
  for (int ci=0;ci<128;ci++){
    float v = fmaxf(__ldg(ip + (size_t)ci*1024), 0.f);
    const float4* wr = reinterpret_cast<const float4*>(&swT[ci*64]);
    #pragma unroll
    for (int q=0;q<16;q++){
      float4 wv = wr[q];
      acc[4*q  ]=fmaf(wv.x,v,acc[4*q  ]); acc[4*q+1]=fmaf(wv.y,v,acc[4*q+1]);
      acc[4*q+2]=fmaf(wv.z,v,acc[4*q+2]); acc[4*q+3]=fmaf(wv.w,v,acc[4*q+3]);
    }
  }
  float4* zp = reinterpret_cast<float4*>(g_Z + (size_t)(b*1024+p)*64);
  #pragma unroll
  for (int q=0;q<16;q++) zp[q] = make_float4(acc[4*q],acc[4*q+1],acc[4*q+2],acc[4*q+3]);
}

// ---------------- VQ: argmin via f32x2 (bit-identical chains) ----------------
__global__ void k_vq(const float* __restrict__ emb){
  __shared__ __align__(16) float sE[128*64];
  __shared__ float sQ[128];
  __shared__ double sred[128];
  int tid = threadIdx.x;
  int n = blockIdx.x*128 + tid;
  int b = n >> 10, p = n & 1023;
  __align__(16) float zr[64];
  {
    const float4* zp = reinterpret_cast<const float4*>(g_Z + (size_t)n*64);
    float4* zr4 = reinterpret_cast<float4*>(zr);
    #pragma unroll
    for (int i=0;i<16;i++) zr4[i] = zp[i];
  }
  const u64* z2 = reinterpret_cast<const u64*>(zr);
  float best = FLT_MAX; int bi = 0;
  for (int c=0;c<8;c++){
    const float4* src = reinterpret_cast<const float4*>(emb) + (size_t)c*2048;
    float4* dst = reinterpret_cast<float4*>(sE);
    #pragma unroll
    for (int r=0;r<16;r++) dst[tid + r*128] = src[tid + r*128];
    sQ[tid] = g_ESQ[c*128+tid];
    __syncthreads();
    for (int kk=0;kk<128;kk++){
      const ulonglong2* e2 = reinterpret_cast<const ulonglong2*>(sE + kk*64);
      u64 p01 = 0ull, p23 = 0ull;
      #pragma unroll
      for (int i=0;i<16;i++){
        ulonglong2 ev = e2[i];
        fma2(p01, ev.x, z2[2*i]);
        fma2(p23, ev.y, z2[2*i+1]);
      }
      float2 f01 = up2(p01), f23 = up2(p23);
      float sc = sQ[kk] - 2.f*((f01.x+f01.y)+(f23.x+f23.y));
      if (sc < best){ best = sc; bi = c*128+kk; }   // strict < : first min
    }
    __syncthreads();
  }
  g_IDX[n] = bi;
  const float* er = emb + (size_t)bi*64;
  float ls = 0.f;
  #pragma unroll
  for (int d=0; d<64; d++){
    float e = __ldg(er+d);
    g_ZQ[(size_t)(b*64+d)*1024 + p] = e;
    float df = e - zr[d];
    ls = fmaf(df,df,ls);
  }
  sred[tid] = (double)ls;
  __syncthreads();
  #pragma unroll
  for (int s=64;s>0;s>>=1){
    if (tid<s) sred[tid] += sred[tid+s];
    __syncthreads();
  }
  if (tid==0) g_PART[blockIdx.x] = sred[0];
}

// ---------------- ConvTranspose 4x4 s2 p1: 128@32 -> 64@64, 2-ci stages ------
// COT=16: launch with gridDim.x == 4
__global__ void __launch_bounds__(256,2)
k_convT2s(const float* __restrict__ bias)
{
  constexpr int CP = 8;
  __shared__ __align__(16) float sIn[2][2][400];
  __shared__ __align__(16) float sW [2][512];
  int co0 = blockIdx.x*16;
  int yq0 = blockIdx.y*8;
  int b   = blockIdx.z;
  int tid = threadIdx.x;
  int tx = tid & 31, ty = tid >> 5;

  u64 acc[CP][4];
  #pragma unroll
  for (int j=0;j<CP;j++)
    #pragma unroll
    for (int q=0;q<4;q++) acc[j][q] = 0ull;

  const float* ipb = g_D1 + (size_t)b*128*1024;
  int r0 = tid/34, c0 = tid - r0*34;
  int r1 = (tid+256)/34, c1 = (tid+256) - r1*34;
  bool has1 = (tid+256) < 340;
  int giy0 = yq0-1+r0, gix0 = c0-1;
  int giy1 = yq0-1+r1, gix1 = c1-1;
  bool in0 = (giy0>=0 && giy0<32 && gix0>=0 && gix0<32);
  bool in1 = has1 && (giy1>=0 && giy1<32 && gix1>=0 && gix1<32);
  int off0 = giy0*32+gix0, off1 = giy1*32+gix1;
  const float* wsrc = g_TW_D2 + (size_t)(tid>>4)*64 + co0 + (tid&15);

  float a0,a1,b0v,b1v;
  a0  = in0 ? fmaxf(__ldg(ipb + off0),0.f) : 0.f;
  a1  = in1 ? fmaxf(__ldg(ipb + off1),0.f) : 0.f;
  b0v = in0 ? fmaxf(__ldg(ipb + 1024 + off0),0.f) : 0.f;
  b1v = in1 ? fmaxf(__ldg(ipb + 1024 + off1),0.f) : 0.f;
  float wa = __ldg(wsrc);
  float wb = __ldg(wsrc + 1024);

  int pb = 0;
  for (int ci=0; ci<128; ci+=2){
    sIn[pb][0][r0*40 + c0] = a0;
    if (has1) sIn[pb][0][r1*40 + c1] = a1;
    sIn[pb][1][r0*40 + c0] = b0v;
    if (has1) sIn[pb][1][r1*40 + c1] = b1v;
    sW[pb][tid] = wa;
    sW[pb][256+tid] = wb;
    __syncthreads();
    if (ci+2 < 128){
      const float* ip0 = ipb + (size_t)(ci+2)*1024;
      const float* ip1 = ipb + (size_t)(ci+3)*1024;
      a0  = in0 ? fmaxf(__ldg(ip0 + off0),0.f) : 0.f;
      a1  = in1 ? fmaxf(__ldg(ip0 + off1),0.f) : 0.f;
      b0v = in0 ? fmaxf(__ldg(ip1 + off0),0.f) : 0.f;
      b1v = in1 ? fmaxf(__ldg(ip1 + off1),0.f) : 0.f;
      wa = __ldg(wsrc + (size_t)(ci+2)*1024);
      wb = __ldg(wsrc + (size_t)(ci+3)*1024);
    }
    #pragma unroll
    for (int pl=0; pl<2; pl++){
      u64 rp[9];
      #pragma unroll
      for (int dy=0;dy<3;dy++)
        #pragma unroll
        for (int dx=0;dx<3;dx++){
          float rv = sIn[pb][pl][(ty+dy)*40 + tx+dx];
          rp[dy*3+dx] = pk2(rv,rv);
        }
      #pragma unroll
      for (int ky=0;ky<4;ky++){
        #pragma unroll
        for (int kx=0;kx<4;kx++){
          u64 rv = rp[((4-ky)>>1)*3 + ((4-kx)>>1)];
          const int pp = (((ky&1)^1)<<1) | ((kx&1)^1);
          const ulonglong2* wq = reinterpret_cast<const ulonglong2*>(&sW[pb][pl*256 + (ky*4+kx)*16]);
          #pragma unroll
          for (int j2=0;j2<CP/2;j2++){
            ulonglong2 wv = wq[j2];
            fma2(acc[2*j2  ][pp], wv.x, rv);
            fma2(acc[2*j2+1][pp], wv.y, rv);
          }
        }
      }
    }
    pb ^= 1;
  }
  int yq = yq0 + ty;
  #pragma unroll
  for (int j=0;j<CP;j++){
    float2 f0=up2(acc[j][0]), f1=up2(acc[j][1]), f2=up2(acc[j][2]), f3=up2(acc[j][3]);
    float bvx = __ldg(bias+co0+2*j), bvy = __ldg(bias+co0+2*j+1);
    float* opx = g_U1 + (size_t)(b*64+co0+2*j)*4096;
    float* opy = g_U1 + (size_t)(b*64+co0+2*j+1)*4096;
    float2 ex0 = make_float2(fmaxf(f0.x+bvx,0.f), fmaxf(f1.x+bvx,0.f));
    float2 ex1 = make_float2(fmaxf(f2.x+bvx,0.f), fmaxf(f3.x+bvx,0.f));
    float2 ey0 = make_float2(fmaxf(f0.y+bvy,0.f), fmaxf(f1.y+bvy,0.f));
    float2 ey1 = make_float2(fmaxf(f2.y+bvy,0.f), fmaxf(f3.y+bvy,0.f));
    *reinterpret_cast<float2*>(opx + (2*yq+0)*64 + 2*tx) = ex0;
    *reinterpret_cast<float2*>(opx + (2*yq+1)*64 + 2*tx) = ex1;
    *reinterpret_cast<float2*>(opy + (2*yq+0)*64 + 2*tx) = ey0;
    *reinterpret_cast<float2*>(opy + (2*yq+1)*64 + 2*tx) = ey1;
  }
}

// ---------------- ConvTranspose 4x4 s2 p1: 64@64 -> 3@128 (recon) ------------
__global__ void __launch_bounds__(256,2)
k_convT3s(const float* __restrict__ bias, float* __restrict__ out)
{
  __shared__ __align__(16) float sIn[2][10*40];
  __shared__ __align__(16) float sW [2][64];
  int xq0 = blockIdx.x*32;
  int yq0 = blockIdx.y*8;
  int b   = blockIdx.z;
  int tid = threadIdx.x;
  int tx = tid & 31, ty = tid >> 5;

  float acc[3][4];
  #pragma unroll
  for (int j=0;j<3;j++)
    #pragma unroll
    for (int q=0;q<4;q++) acc[j][q]=0.f;

  const float* ipb = g_U1 + (size_t)b*64*4096;
  int r0 = tid/34, c0 = tid - r0*34;
  int r1 = (tid+256)/34, c1 = (tid+256) - r1*34;
  bool has1 = (tid+256) < 340;
  bool wact = tid < 64;
  float s0, s1 = 0.f;
  {
    int giy = yq0-1+r0, gix = xq0-1+c0;
    s0 = (giy>=0&&giy<64&&gix>=0&&gix<64)?__ldg(ipb+giy*64+gix):0.f;
    if (has1){
      int giy1 = yq0-1+r1, gix1 = xq0-1+c1;
      s1 = (giy1>=0&&giy1<64&&gix1>=0&&gix1<64)?__ldg(ipb+giy1*64+gix1):0.f;
    }
  }
  float wv0 = wact ? __ldg(g_TW_D3 + tid) : 0.f;
  int pb = 0;
  for (int ci=0; ci<64; ci++){
    sIn[pb][r0*40 + c0] = s0;
    if (has1) sIn[pb][r1*40 + c1] = s1;
    if (wact) sW[pb][tid] = wv0;
    __syncthreads();
    if (ci+1 < 64){
      const float* ip = ipb + (size_t)(ci+1)*4096;
      int giy = yq0-1+r0, gix = xq0-1+c0;
      s0 = (giy>=0&&giy<64&&gix>=0&&gix<64)?__ldg(ip+giy*64+gix):0.f;
      if (has1){
        int giy1 = yq0-1+r1, gix1 = xq0-1+c1;
        s1 = (giy1>=0&&giy1<64&&gix1>=0&&gix1<64)?__ldg(ip+giy1*64+gix1):0.f;
      }
      if (wact) wv0 = __ldg(g_TW_D3 + (size_t)(ci+1)*64 + tid);
    }
    float r3[3][3];
    #pragma unroll
    for (int dy=0;dy<3;dy++)
      #pragma unroll
      for (int dx=0;dx<3;dx++)
        r3[dy][dx] = sIn[pb][(ty+dy)*40 + tx+dx];
    #pragma unroll
    for (int ky=0;ky<4;ky++){
      #pragma unroll
      for (int kx=0;kx<4;kx++){
        float rv = r3[(4-ky)>>1][(4-kx)>>1];
        const int pp = (((ky&1)^1)<<1) | ((kx&1)^1);
        float4 wv = *reinterpret_cast<const float4*>(&sW[pb][(ky*4+kx)*4]);
        acc[0][pp]=fmaf(wv.x,rv,acc[0][pp]);
        acc[1][pp]=fmaf(wv.y,rv,acc[1][pp]);
        acc[2][pp]=fmaf(wv.z,rv,acc[2][pp]);
      }
    }
    pb ^= 1;
  }
  int yq = yq0 + ty, xq = xq0 + tx;
  #pragma unroll
  for (int j=0;j<3;j++){
    float bv = __ldg(bias+j);
    float* op = out + (size_t)(b*3+j)*16384;
    float2 e0 = make_float2(acc[j][0]+bv, acc[j][1]+bv);
    float2 e1 = make_float2(acc[j][2]+bv, acc[j][3]+bv);
    *reinterpret_cast<float2*>(op + (2*yq+0)*128 + 2*xq) = e0;
    *reinterpret_cast<float2*>(op + (2*yq+1)*128 + 2*xq) = e1;
  }
}

// ---------------- finalize: idx as float -------------------------------------
__global__ void k_final(float* __restrict__ out){
  int t = blockIdx.x*blockDim.x + threadIdx.x;
  if (t < 65536) out[3145730 + t] = (float)g_IDX[t];
}

// ---------------- loss: parallel deterministic double reduction --------------
__global__ void k_loss(float* __restrict__ out){
  __shared__ double sd[512];
  int t = threadIdx.x;
  sd[t] = g_PART[t];
  __syncthreads();
  #pragma unroll
  for (int s=256;s>0;s>>=1){
    if (t<s) sd[t] += sd[t+s];
    __syncthreads();
  }
  if (t==0){
    float m = (float)(sd[0] / 4194304.0);
    out[3145728] = m;   // codebook_loss
    out[3145729] = m;   // commitment_loss (identical value)
  }
}

// ---------------- launcher ---------------------------------------------------
extern "C" void kernel_launch(void* const* d_in, const int* in_sizes, int n_in,
                              void* d_out, int out_size)
{
  const float* patch=(const float*)d_in[0];
  const float* ew1=(const float*)d_in[1];  const float* eb1=(const float*)d_in[2];
  const float* ew2=(const float*)d_in[3];  const float* eb2=(const float*)d_in[4];
  const float* ew3=(const float*)d_in[5];  const float* eb3=(const float*)d_in[6];
  const float* er1a=(const float*)d_in[7]; const float* er1b=(const float*)d_in[8];
  const float* er2a=(const float*)d_in[9]; const float* er2b=(const float*)d_in[10];
  const float* pqw=(const float*)d_in[11]; const float* pqb=(const float*)d_in[12];
  const float* emb=(const float*)d_in[13];
  const float* dw1=(const float*)d_in[14]; const float* db1=(const float*)d_in[15];
  const float* dr1a=(const float*)d_in[16];const float* dr1b=(const float*)d_in[17];
  const float* dr2a=(const float*)d_in[18];const float* dr2b=(const float*)d_in[19];
  const float* dw2=(const float*)d_in[20]; const float* db2=(const float*)d_in[21];
  const float* dw3=(const float*)d_in[22]; const float* db3=(const float*)d_in[23];
  float* out = (float*)d_out;
  (void)in_sizes; (void)n_in; (void)out_size;

  // esq + all weight transposes in one kernel
  k_prep<<<2492,256>>>(emb, ew1, ew2, ew3, er1a, er2a, dr1a, dr2a, dw1, dw2, dw3);

  // encoder
  k_conv4s<3,64,128,16> <<<dim3(4,4,NB),256>>>(patch, -1, 10, eb1, 0);
  k_conv4s<64,128,64,8> <<<dim3(16,1,NB),256>>>(nullptr, 0, 11, eb2, 1);
  k_conv3d<128,128,8,false,false,true><<<dim3(16,NB/2),256>>>(1, 12, eb3, 2);
  // residual block 1
  k_conv3d<128,32,8,true,true,false><<<dim3(4,NB/2),256>>>(2, 13, nullptr, 3);
  k_res1x1v<<<dim3(4,NB),256>>>(3, er1b, 2);
  // residual block 2
  k_conv3d<128,32,8,true,true,false><<<dim3(4,NB/2),256>>>(2, 14, nullptr, 3);
  k_res1x1v<<<dim3(4,NB),256>>>(3, er2b, 2);
  // pre-quant (relu fused into input)
  k_pqv<<<dim3(4,NB),256>>>(2, pqw, pqb);
  // vector quantization
  k_vq<<<512,128>>>(emb);

  // decoder
  k_conv3d<64,128,8,false,false,true><<<dim3(16,NB/2),256>>>(5, 17, db1, 6);
  k_conv3d<128,32,8,true,true,false><<<dim3(4,NB/2),256>>>(6, 15, nullptr, 3);
  k_res1x1v<<<dim3(4,NB),256>>>(3, dr1b, 6);
  k_conv3d<128,32,8,true,true,false><<<dim3(4,NB/2),256>>>(6, 16, nullptr, 3);
  k_res1x1v<<<dim3(4,NB),256>>>(3, dr2b, 6);
  k_convT2s<<<dim3(4,4,NB),256>>>(db2);
  k_convT3s<<<dim3(2,8,NB),256>>>(db3, out);

  // losses + indices
  k_loss<<<1,512>>>(out);
  k_final<<<256,256>>>(out);
}

// round 16
// speedup vs baseline: 1.0507x; 1.0507x over previous
#include <cuda_runtime.h>
#include <cfloat>
#include <cstddef>

#define NB 64   // batch

typedef unsigned long long u64;

// ---- packed f32x2 helpers ---------------------------------------------------
__device__ __forceinline__ u64 pk2(float lo, float hi){
  u64 r; asm("mov.b64 %0,{%1,%2};" : "=l"(r) : "f"(lo), "f"(hi)); return r;
}
__device__ __forceinline__ float2 up2(u64 v){
  float2 f; asm("mov.b64 {%0,%1},%2;" : "=f"(f.x), "=f"(f.y) : "l"(v)); return f;
}
__device__ __forceinline__ void fma2(u64 &d, u64 a, u64 b){
  asm("fma.rn.f32x2 %0,%1,%2,%0;" : "+l"(d) : "l"(a), "l"(b));
}

// ---------------- scratch buffers (device globals; no allocations) ----------
__device__ __align__(16) float g_A1[(size_t)NB*64*64*64];   // enc conv1 out
__device__ __align__(16) float g_A2[(size_t)NB*128*32*32];  // enc conv2 out
__device__ __align__(16) float g_A3[(size_t)NB*128*32*32];  // enc conv3/res
__device__ __align__(16) float g_T [(size_t)NB*32*32*32];   // res 3x3 temp
__device__ __align__(16) float g_Z [(size_t)NB*32*32*64];   // z NHWC
__device__ __align__(16) float g_ZQ[(size_t)NB*64*32*32];   // z_q NCHW
__device__ __align__(16) float g_D1[(size_t)NB*128*32*32];  // dec trunk
__device__ __align__(16) float g_U1[(size_t)NB*64*64*64];   // dec upsample
// pre-transposed weights: [ci][tap][co]
__device__ __align__(16) float g_TW_E1[3*16*64];
__device__ __align__(16) float g_TW_E2[64*16*128];
__device__ __align__(16) float g_TW_E3[128*9*128];
__device__ __align__(16) float g_TW_R1A[128*9*32];
__device__ __align__(16) float g_TW_R2A[128*9*32];
__device__ __align__(16) float g_TW_DR1A[128*9*32];
__device__ __align__(16) float g_TW_DR2A[128*9*32];
__device__ __align__(16) float g_TW_DEC[64*9*128];          // flipped dw1
__device__ __align__(16) float g_TW_D2[128*16*64];
__device__ __align__(16) float g_TW_D3[64*16*4];            // co padded 3->4
__device__ float  g_ESQ[1024];
__device__ int    g_IDX[65536];
__device__ double g_PART[512];

__device__ __forceinline__ float* gbuf(int id){
  switch(id){
    case 0: return g_A1; case 1: return g_A2; case 2: return g_A3;
    case 3: return g_T;  case 4: return g_Z;  case 5: return g_ZQ;
    case 6: return g_D1; case 7: return g_U1;
    case 10: return g_TW_E1;  case 11: return g_TW_E2;  case 12: return g_TW_E3;
    case 13: return g_TW_R1A; case 14: return g_TW_R2A; case 15: return g_TW_DR1A;
    case 16: return g_TW_DR2A;case 17: return g_TW_DEC; case 18: return g_TW_D2;
    default: return g_TW_D3;
  }
}
__device__ __forceinline__ const float* gbuf_c(int id, const float* ext){
  if (id < 0) return ext;
  return gbuf(id);
}

// ---------------- merged prep: esq + all weight transposes -------------------
__device__ __forceinline__ void trA_i(const float* __restrict__ w, float* T,
                                      int CI,int CO,int KK,int t){
  int co = t/(CI*KK); int r = t%(CI*KK); int ci = r/KK, kk = r%KK;
  T[((size_t)ci*KK+kk)*CO+co] = w[t];
}
__device__ __forceinline__ void trB_i(const float* __restrict__ w, float* T,
                                      int CI,int CO,int KK,int COP,int t){
  int ci = t/(CO*KK); int r = t%(CO*KK); int co = r/KK, kk = r%KK;
  T[((size_t)ci*KK+kk)*COP+co] = w[t];
}

__global__ void k_prep(const float* __restrict__ emb,
                       const float* __restrict__ ew1, const float* __restrict__ ew2,
                       const float* __restrict__ ew3,
                       const float* __restrict__ er1a, const float* __restrict__ er2a,
                       const float* __restrict__ dr1a, const float* __restrict__ dr2a,
                       const float* __restrict__ dw1, const float* __restrict__ dw2,
                       const float* __restrict__ dw3)
{
  int t = blockIdx.x*256 + threadIdx.x;
  if (t < 1024){
    const float4* e = reinterpret_cast<const float4*>(emb + (size_t)t*64);
    float s = 0.f;
    #pragma unroll
    for (int i=0;i<16;i++){
      float4 v = e[i];
      s = fmaf(v.x,v.x,fmaf(v.y,v.y,fmaf(v.z,v.z,fmaf(v.w,v.w,s))));
    }
    g_ESQ[t] = s; return;
  } t -= 1024;
  if (t < 3072){ trA_i(ew1, g_TW_E1, 3,64,16, t); return; } t -= 3072;
  if (t < 131072){ trA_i(ew2, g_TW_E2, 64,128,16, t); return; } t -= 131072;
  if (t < 147456){ trA_i(ew3, g_TW_E3, 128,128,9, t); return; } t -= 147456;
  if (t < 36864){ trA_i(er1a, g_TW_R1A, 128,32,9, t); return; } t -= 36864;
  if (t < 36864){ trA_i(er2a, g_TW_R2A, 128,32,9, t); return; } t -= 36864;
  if (t < 36864){ trA_i(dr1a, g_TW_DR1A, 128,32,9, t); return; } t -= 36864;
  if (t < 36864){ trA_i(dr2a, g_TW_DR2A, 128,32,9, t); return; } t -= 36864;
  if (t < 73728){
    int ci = t/(128*9); int r = t%(128*9); int co = r/9, kk = r%9;
    int ky = kk/3, kx = kk%3;
    g_TW_DEC[((size_t)ci*9 + (2-ky)*3 + (2-kx))*128 + co] = dw1[t]; return;
  } t -= 73728;
  if (t < 131072){ trB_i(dw2, g_TW_D2, 128,64,16,64, t); return; } t -= 131072;
  if (t < 3072){ trB_i(dw3, g_TW_D3, 64,3,16,4, t); }
}

// ---------------- 3x3 s1 p1 conv at 32x32, f32x2, 2-ci stages ----------------
template<int CIN,int COUT,int COT,bool RIN,bool ROUT,bool HASB>
__global__ void __launch_bounds__(256,3)
k_conv3s(int in_id, int w_id, const float* __restrict__ bias, int out_id)
{
  constexpr int CP   = COT/2;
  constexpr int WSZ  = 9*COT;        // weight floats per plane
  constexpr int WTOT = 2*WSZ;
  static_assert(WTOT <= 256, "weight staging assumes one element per thread");
  static_assert(CIN % 2 == 0, "paired ci staging");
  __shared__ __align__(16) float sIn[2][2][34*40];
  __shared__ __align__(16) float sW [2][WTOT];
  const float* in = gbuf_c(in_id, nullptr);
  const float* W  = gbuf_c(w_id, nullptr);
  float* out = gbuf(out_id);
  int co0 = blockIdx.x*COT;
  int b   = blockIdx.y;
  int tid = threadIdx.x;
  int tx = tid & 7, ty = tid >> 3;
  int x0 = tx*4;

  for (int i=tid; i<34*40; i+=256){
    sIn[0][0][i]=0.f; sIn[0][1][i]=0.f; sIn[1][0][i]=0.f; sIn[1][1][i]=0.f;
  }
  __syncthreads();

  u64 acc[CP][4];
  #pragma unroll
  for (int j=0;j<CP;j++){
    u64 bp = HASB ? pk2(__ldg(bias+co0+2*j), __ldg(bias+co0+2*j+1)) : 0ull;
    #pragma unroll
    for (int p=0;p<4;p++) acc[j][p] = bp;
  }

  const float* ipb = in + (size_t)b*CIN*1024;
  bool wact = tid < WTOT;
  int wpl = tid / WSZ, wrem = tid % WSZ;
  int wtap = wrem / COT, wco = wrem % COT;
  const float* wbase = W + ((size_t)wpl*9 + wtap)*COUT + co0 + wco;

  float4 va = __ldg(reinterpret_cast<const float4*>(ipb) + tid);
  float4 vc = __ldg(reinterpret_cast<const float4*>(ipb + 1024) + tid);
  if (RIN){
    va.x=fmaxf(va.x,0.f); va.y=fmaxf(va.y,0.f); va.z=fmaxf(va.z,0.f); va.w=fmaxf(va.w,0.f);
    vc.x=fmaxf(vc.x,0.f); vc.y=fmaxf(vc.y,0.f); vc.z=fmaxf(vc.z,0.f); vc.w=fmaxf(vc.w,0.f);
  }
  float wv0 = wact ? __ldg(wbase) : 0.f;

  int pb = 0;
  for (int ci=0; ci<CIN; ci+=2){
    float* sp0 = &sIn[pb][0][(ty+1)*40 + 1 + x0];
    sp0[0]=va.x; sp0[1]=va.y; sp0[2]=va.z; sp0[3]=va.w;
    float* sp1 = &sIn[pb][1][(ty+1)*40 + 1 + x0];
    sp1[0]=vc.x; sp1[1]=vc.y; sp1[2]=vc.z; sp1[3]=vc.w;
    if (wact) sW[pb][tid] = wv0;
    __syncthreads();
    if (ci+2 < CIN){
      va = __ldg(reinterpret_cast<const float4*>(ipb + (size_t)(ci+2)*1024) + tid);
      vc = __ldg(reinterpret_cast<const float4*>(ipb + (size_t)(ci+3)*1024) + tid);
      if (RIN){
        va.x=fmaxf(va.x,0.f); va.y=fmaxf(va.y,0.f); va.z=fmaxf(va.z,0.f); va.w=fmaxf(va.w,0.f);
        vc.x=fmaxf(vc.x,0.f); vc.y=fmaxf(vc.y,0.f); vc.z=fmaxf(vc.z,0.f); vc.w=fmaxf(vc.w,0.f);
      }
      if (wact) wv0 = __ldg(wbase + (size_t)(ci+2)*9*COUT);
    }
    #pragma unroll
    for (int pl=0; pl<2; pl++){
      #pragma unroll
      for (int ky=0;ky<3;ky++){
        const float* row = &sIn[pb][pl][(ty+ky)*40 + x0];
        float4 a = *reinterpret_cast<const float4*>(row);
        float2 e45 = *reinterpret_cast<const float2*>(row+4);   // aligned LDS.64
        u64 vb[6];
        vb[0]=pk2(a.x,a.x); vb[1]=pk2(a.y,a.y); vb[2]=pk2(a.z,a.z);
        vb[3]=pk2(a.w,a.w); vb[4]=pk2(e45.x,e45.x); vb[5]=pk2(e45.y,e45.y);
        #pragma unroll
        for (int kx=0;kx<3;kx++){
          const ulonglong2* wq = reinterpret_cast<const ulonglong2*>(&sW[pb][pl*WSZ + (ky*3+kx)*COT]);
          #pragma unroll
          for (int j2=0;j2<CP/2;j2++){
            ulonglong2 wv = wq[j2];
            #pragma unroll
            for (int p=0;p<4;p++){
              fma2(acc[2*j2  ][p], wv.x, vb[kx+p]);
              fma2(acc[2*j2+1][p], wv.y, vb[kx+p]);
            }
          }
        }
      }
    }
    pb ^= 1;
  }
  #pragma unroll
  for (int j=0;j<CP;j++){
    float2 f0=up2(acc[j][0]), f1=up2(acc[j][1]), f2=up2(acc[j][2]), f3=up2(acc[j][3]);
    float4 oe = make_float4(f0.x,f1.x,f2.x,f3.x);
    float4 oo = make_float4(f0.y,f1.y,f2.y,f3.y);
    if (ROUT){
      oe.x=fmaxf(oe.x,0.f); oe.y=fmaxf(oe.y,0.f); oe.z=fmaxf(oe.z,0.f); oe.w=fmaxf(oe.w,0.f);
      oo.x=fmaxf(oo.x,0.f); oo.y=fmaxf(oo.y,0.f); oo.z=fmaxf(oo.z,0.f); oo.w=fmaxf(oo.w,0.f);
    }
    *reinterpret_cast<float4*>(out + ((size_t)(b*COUT+co0+2*j  )*32 + ty)*32 + x0) = oe;
    *reinterpret_cast<float4*>(out + ((size_t)(b*COUT+co0+2*j+1)*32 + ty)*32 + x0) = oo;
  }
}

// ---------------- 4x4 s2 p1 conv, f32x2, dbl-buf input+weights ---------------
template<int CIN,int COUT,int HIN,int COT>
__global__ void __launch_bounds__(256,2)
k_conv4s(const float* __restrict__ ext_in, int in_id, int w_id,
         const float* __restrict__ bias, int out_id)
{
  constexpr int CP = COT/2;
  constexpr int HOUT = HIN/2;
  constexpr int XT   = HOUT/32;
  constexpr int WSZ  = 16*COT;
  static_assert(WSZ <= 256, "weight staging assumes one element per thread");
  __shared__ __align__(16) float sIn[2][66*72];
  __shared__ __align__(16) float sW [2][WSZ];
  const float* in = gbuf_c(in_id, ext_in);
  const float* W  = gbuf_c(w_id, nullptr);
  float* out = gbuf(out_id);
  int co0 = blockIdx.x*COT;
  int oy0 = (blockIdx.y/XT)*32, ox0 = (blockIdx.y%XT)*32;
  int b = blockIdx.z;
  int tid = threadIdx.x;
  int tx = tid & 7, ty = tid >> 3;
  int x0 = tx*4;

  u64 acc[CP][4];
  #pragma unroll
  for (int j=0;j<CP;j++){
    u64 bp = pk2(__ldg(bias+co0+2*j), __ldg(bias+co0+2*j+1));
    #pragma unroll
    for (int p=0;p<4;p++) acc[j][p] = bp;
  }

  int iy0 = oy0*2 - 1, ix0 = ox0*2 - 1;
  int wk = tid / COT, wj = tid % COT;
  bool wact = tid < WSZ;
  const float* wsrc0 = W + (size_t)wk*COUT + co0 + wj;

  float sreg[18];
  {
    const float* ip = in + (size_t)b*CIN*HIN*HIN;
    #pragma unroll
    for (int t=0;t<18;t++){
      int s = tid + t*256; float v = 0.f;
      if (s < 4356){
        int r = s/66, c = s - r*66;
        int giy = iy0 + r, gix = ix0 + c;
        if (giy>=0 && giy<HIN && gix>=0 && gix<HIN) v = __ldg(ip + (size_t)giy*HIN + gix);
      }
      sreg[t] = v;
    }
  }
  float wv0 = wact ? __ldg(wsrc0) : 0.f;

  int pb = 0;
  for (int ci=0; ci<CIN; ci++){
    #pragma unroll
    for (int t=0;t<18;t++){
      int s = tid + t*256;
      if (s < 4356){ int r = s/66, c = s - r*66; sIn[pb][r*72 + c] = sreg[t]; }
    }
    if (wact) sW[pb][tid] = wv0;
    __syncthreads();
    if (ci+1 < CIN){
      const float* ip = in + (size_t)(b*CIN+ci+1)*HIN*HIN;
      #pragma unroll
      for (int t=0;t<18;t++){
        int s = tid + t*256; float v = 0.f;
        if (s < 4356){
          int r = s/66, c = s - r*66;
          int giy = iy0 + r, gix = ix0 + c;
          if (giy>=0 && giy<HIN && gix>=0 && gix<HIN) v = __ldg(ip + (size_t)giy*HIN + gix);
        }
        sreg[t] = v;
      }
      if (wact) wv0 = __ldg(wsrc0 + (size_t)(ci+1)*16*COUT);
    }
    #pragma unroll
    for (int ky=0;ky<4;ky++){
      const float* row = &sIn[pb][(2*ty+ky)*72 + 2*x0];
      float4 a  = *reinterpret_cast<const float4*>(row);
      float4 bq = *reinterpret_cast<const float4*>(row+4);
      float2 e89 = *reinterpret_cast<const float2*>(row+8);
      u64 vb[10];
      vb[0]=pk2(a.x,a.x); vb[1]=pk2(a.y,a.y); vb[2]=pk2(a.z,a.z); vb[3]=pk2(a.w,a.w);
      vb[4]=pk2(bq.x,bq.x); vb[5]=pk2(bq.y,bq.y); vb[6]=pk2(bq.z,bq.z); vb[7]=pk2(bq.w,bq.w);
      vb[8]=pk2(e89.x,e89.x); vb[9]=pk2(e89.y,e89.y);
      #pragma unroll
      for (int kx=0;kx<4;kx++){
        const ulonglong2* wq = reinterpret_cast<const ulonglong2*>(&sW[pb][(ky*4+kx)*COT]);
        #pragma unroll
        for (int j2=0;j2<CP/2;j2++){
          ulonglong2 wv = wq[j2];
          #pragma unroll
          for (int p=0;p<4;p++){
            fma2(acc[2*j2  ][p], wv.x, vb[kx+2*p]);
            fma2(acc[2*j2+1][p], wv.y, vb[kx+2*p]);
          }
        }
      }
    }
    pb ^= 1;
  }
  #pragma unroll
  for (int j=0;j<CP;j++){
    float2 f0=up2(acc[j][0]), f1=up2(acc[j][1]), f2=up2(acc[j][2]), f3=up2(acc[j][3]);
    float4 oe = make_float4(fmaxf(f0.x,0.f),fmaxf(f1.x,0.f),fmaxf(f2.x,0.f),fmaxf(f3.x,0.f));
    float4 oo = make_float4(fmaxf(f0.y,0.f),fmaxf(f1.y,0.f),fmaxf(f2.y,0.f),fmaxf(f3.y,0.f));
    *reinterpret_cast<float4*>(out + ((size_t)(b*COUT+co0+2*j  )*HOUT + oy0+ty)*HOUT + ox0+x0) = oe;
    *reinterpret_cast<float4*>(out + ((size_t)(b*COUT+co0+2*j+1)*HOUT + oy0+ty)*HOUT + ox0+x0) = oo;
  }
}

// ---------------- 1x1 conv residual-add, f32x2 over co pairs -----------------
__global__ void __launch_bounds__(256)
k_res1x1v(int t_id, const float* __restrict__ w, int x_id)
{
  __shared__ __align__(16) u64 swp[64*32];   // [co2][ci] packed (co, co+1) pairs
  const float* t = gbuf_c(t_id, nullptr);
  float* x = gbuf(x_id);
  int b = blockIdx.y, p = blockIdx.x*256 + threadIdx.x;
  for (int i=threadIdx.x; i<2048; i+=256){
    int co2 = i >> 5, ci = i & 31;
    swp[i] = pk2(__ldg(w + (size_t)(2*co2)*32 + ci),
                 __ldg(w + (size_t)(2*co2+1)*32 + ci));
  }
  __syncthreads();
  u64 rvp[32];
  #pragma unroll
  for (int ci=0;ci<32;ci++){
    float v = __ldg(t + (size_t)(b*32+ci)*1024 + p);
    rvp[ci] = pk2(v,v);
  }
  #pragma unroll 2
  for (int co2=0;co2<64;co2++){
    u64 a = 0ull;
    const u64* wr = &swp[co2*32];
    #pragma unroll
    for (int ci=0;ci<32;ci++) fma2(a, wr[ci], rvp[ci]);
    float2 f = up2(a);
    x[(size_t)(b*128+2*co2  )*1024 + p] += f.x;
    x[(size_t)(b*128+2*co2+1)*1024 + p] += f.y;
  }
}

// ---------------- pre-quant 1x1: relu(in) -> z NHWC, f32x2 over d pairs ------
__global__ void __launch_bounds__(256)
k_pqv(int in_id, const float* __restrict__ w, const float* __restrict__ bias)
{
  __shared__ __align__(16) u64 swp[128*32];  // [ci][d2] packed (d, d+1) pairs
  const float* h = gbuf_c(in_id, nullptr);
  int b = blockIdx.y, p = blockIdx.x*256 + threadIdx.x;
  for (int i=threadIdx.x; i<4096; i+=256){
    int ci = i >> 5, d2 = i & 31;
    swp[i] = pk2(__ldg(w + (size_t)(2*d2)*128 + ci),
                 __ldg(w + (size_t)(2*d2+1)*128 + ci));
  }
  __syncthreads();
  u64 acc2[32];
  #pragma unroll
  for (int d2=0;d2<32;d2++) acc2[d2] = pk2(__ldg(bias+2*d2), __ldg(bias+2*d2+1));
  const float* ip = h + (size_t)b*128*1024 + p;
  for (int ci=0;ci<128;ci++){
    float v = fmaxf(__ldg(ip + (size_t)ci*1024), 0.f);
    u64 vp = pk2(v,v);
    const u64* wr = &swp[ci*32];
    #pragma unroll
    for (int d2=0;d2<32;d2++) fma2(acc2[d2], wr[d2], vp);
  }
  float4* zp = reinterpret_cast<float4*>(g_Z + (size_t)(b*1024+p)*64);
  #pragma unroll
  for (int q=0;q<16;q++){
    float2 f0 = up2(acc2[2*q]), f1 = up2(acc2[2*q+1]);
    zp[q] = make_float4(f0.x, f0.y, f1.x, f1.y);
  }
}

// ---------------- VQ: argmin via f32x2 (bit-identical chains) ----------------
__global__ void k_vq(const float* __restrict__ emb){
  __shared__ __align__(16) float sE[128*64];
  __shared__ float sQ[128];
  __shared__ double sred[128];
  int tid = threadIdx.x;
  int n = blockIdx.x*128 + tid;
  int b = n >> 10, p = n & 1023;
  __align__(16) float zr[64];
  {
    const float4* zp = reinterpret_cast<const float4*>(g_Z + (size_t)n*64);
    float4* zr4 = reinterpret_cast<float4*>(zr);
    #pragma unroll
    for (int i=0;i<16;i++) zr4[i] = zp[i];
  }
  const u64* z2 = reinterpret_cast<const u64*>(zr);
  float best = FLT_MAX; int bi = 0;
  for (int c=0;c<8;c++){
    const float4* src = reinterpret_cast<const float4*>(emb) + (size_t)c*2048;
    float4* dst = reinterpret_cast<float4*>(sE);
    #pragma unroll
    for (int r=0;r<16;r++) dst[tid + r*128] = src[tid + r*128];
    sQ[tid] = g_ESQ[c*128+tid];
    __syncthreads();
    for (int kk=0;kk<128;kk++){
      const ulonglong2* e2 = reinterpret_cast<const ulonglong2*>(sE + kk*64);
      u64 p01 = 0ull, p23 = 0ull;
      #pragma unroll
      for (int i=0;i<16;i++){
        ulonglong2 ev = e2[i];
        fma2(p01, ev.x, z2[2*i]);
        fma2(p23, ev.y, z2[2*i+1]);
      }
      float2 f01 = up2(p01), f23 = up2(p23);
      float sc = sQ[kk] - 2.f*((f01.x+f01.y)+(f23.x+f23.y));
      if (sc < best){ best = sc; bi = c*128+kk; }   // strict < : first min
    }
    __syncthreads();
  }
  g_IDX[n] = bi;
  const float* er = emb + (size_t)bi*64;
  float ls = 0.f;
  #pragma unroll
  for (int d=0; d<64; d++){
    float e = __ldg(er+d);
    g_ZQ[(size_t)(b*64+d)*1024 + p] = e;
    float df = e - zr[d];
    ls = fmaf(df,df,ls);
  }
  sred[tid] = (double)ls;
  __syncthreads();
  #pragma unroll
  for (int s=64;s>0;s>>=1){
    if (tid<s) sred[tid] += sred[tid+s];
    __syncthreads();
  }
  if (tid==0) g_PART[blockIdx.x] = sred[0];
}

// ---------------- ConvTranspose 4x4 s2 p1: 128@32 -> 64@64, 2-ci stages ------
// COT=16: launch with gridDim.x == 4
__global__ void __launch_bounds__(256,2)
k_convT2s(const float* __restrict__ bias)
{
  constexpr int CP = 8;
  __shared__ __align__(16) float sIn[2][2][400];
  __shared__ __align__(16) float sW [2][512];
  int co0 = blockIdx.x*16;
  int yq0 = blockIdx.y*8;
  int b   = blockIdx.z;
  int tid = threadIdx.x;
  int tx = tid & 31, ty = tid >> 5;

  u64 acc[CP][4];
  #pragma unroll
  for (int j=0;j<CP;j++)
    #pragma unroll
    for (int q=0;q<4;q++) acc[j][q] = 0ull;

  const float* ipb = g_D1 + (size_t)b*128*1024;
  int r0 = tid/34, c0 = tid - r0*34;
  int r1 = (tid+256)/34, c1 = (tid+256) - r1*34;
  bool has1 = (tid+256) < 340;
  int giy0 = yq0-1+r0, gix0 = c0-1;
  int giy1 = yq0-1+r1, gix1 = c1-1;
  bool in0 = (giy0>=0 && giy0<32 && gix0>=0 && gix0<32);
  bool in1 = has1 && (giy1>=0 && giy1<32 && gix1>=0 && gix1<32);
  int off0 = giy0*32+gix0, off1 = giy1*32+gix1;
  const float* wsrc = g_TW_D2 + (size_t)(tid>>4)*64 + co0 + (tid&15);

  float a0,a1,b0v,b1v;
  a0  = in0 ? fmaxf(__ldg(ipb + off0),0.f) : 0.f;
  a1  = in1 ? fmaxf(__ldg(ipb + off1),0.f) : 0.f;
  b0v = in0 ? fmaxf(__ldg(ipb + 1024 + off0),0.f) : 0.f;
  b1v = in1 ? fmaxf(__ldg(ipb + 1024 + off1),0.f) : 0.f;
  float wa = __ldg(wsrc);
  float wb = __ldg(wsrc + 1024);

  int pb = 0;
  for (int ci=0; ci<128; ci+=2){
    sIn[pb][0][r0*40 + c0] = a0;
    if (has1) sIn[pb][0][r1*40 + c1] = a1;
    sIn[pb][1][r0*40 + c0] = b0v;
    if (has1) sIn[pb][1][r1*40 + c1] = b1v;
    sW[pb][tid] = wa;
    sW[pb][256+tid] = wb;
    __syncthreads();
    if (ci+2 < 128){
      const float* ip0 = ipb + (size_t)(ci+2)*1024;
      const float* ip1 = ipb + (size_t)(ci+3)*1024;
      a0  = in0 ? fmaxf(__ldg(ip0 + off0),0.f) : 0.f;
      a1  = in1 ? fmaxf(__ldg(ip0 + off1),0.f) : 0.f;
      b0v = in0 ? fmaxf(__ldg(ip1 + off0),0.f) : 0.f;
      b1v = in1 ? fmaxf(__ldg(ip1 + off1),0.f) : 0.f;
      wa = __ldg(wsrc + (size_t)(ci+2)*1024);
      wb = __ldg(wsrc + (size_t)(ci+3)*1024);
    }
    #pragma unroll
    for (int pl=0; pl<2; pl++){
      u64 rp[9];
      #pragma unroll
      for (int dy=0;dy<3;dy++)
        #pragma unroll
        for (int dx=0;dx<3;dx++){
          float rv = sIn[pb][pl][(ty+dy)*40 + tx+dx];
          rp[dy*3+dx] = pk2(rv,rv);
        }
      #pragma unroll
      for (int ky=0;ky<4;ky++){
        #pragma unroll
        for (int kx=0;kx<4;kx++){
          u64 rv = rp[((4-ky)>>1)*3 + ((4-kx)>>1)];
          const int pp = (((ky&1)^1)<<1) | ((kx&1)^1);
          const ulonglong2* wq = reinterpret_cast<const ulonglong2*>(&sW[pb][pl*256 + (ky*4+kx)*16]);
          #pragma unroll
          for (int j2=0;j2<CP/2;j2++){
            ulonglong2 wv = wq[j2];
            fma2(acc[2*j2  ][pp], wv.x, rv);
            fma2(acc[2*j2+1][pp], wv.y, rv);
          }
        }
      }
    }
    pb ^= 1;
  }
  int yq = yq0 + ty;
  #pragma unroll
  for (int j=0;j<CP;j++){
    float2 f0=up2(acc[j][0]), f1=up2(acc[j][1]), f2=up2(acc[j][2]), f3=up2(acc[j][3]);
    float bvx = __ldg(bias+co0+2*j), bvy = __ldg(bias+co0+2*j+1);
    float* opx = g_U1 + (size_t)(b*64+co0+2*j)*4096;
    float* opy = g_U1 + (size_t)(b*64+co0+2*j+1)*4096;
    float2 ex0 = make_float2(fmaxf(f0.x+bvx,0.f), fmaxf(f1.x+bvx,0.f));
    float2 ex1 = make_float2(fmaxf(f2.x+bvx,0.f), fmaxf(f3.x+bvx,0.f));
    float2 ey0 = make_float2(fmaxf(f0.y+bvy,0.f), fmaxf(f1.y+bvy,0.f));
    float2 ey1 = make_float2(fmaxf(f2.y+bvy,0.f), fmaxf(f3.y+bvy,0.f));
    *reinterpret_cast<float2*>(opx + (2*yq+0)*64 + 2*tx) = ex0;
    *reinterpret_cast<float2*>(opx + (2*yq+1)*64 + 2*tx) = ex1;
    *reinterpret_cast<float2*>(opy + (2*yq+0)*64 + 2*tx) = ey0;
    *reinterpret_cast<float2*>(opy + (2*yq+1)*64 + 2*tx) = ey1;
  }
}

// ---------------- ConvTranspose 4x4 s2 p1: 64@64 -> 3@128 (recon) ------------
__global__ void __launch_bounds__(256,2)
k_convT3s(const float* __restrict__ bias, float* __restrict__ out)
{
  __shared__ __align__(16) float sIn[2][10*40];
  __shared__ __align__(16) float sW [2][64];
  int xq0 = blockIdx.x*32;
  int yq0 = blockIdx.y*8;
  int b   = blockIdx.z;
  int tid = threadIdx.x;
  int tx = tid & 31, ty = tid >> 5;

  float acc[3][4];
  #pragma unroll
  for (int j=0;j<3;j++)
    #pragma unroll
    for (int q=0;q<4;q++) acc[j][q]=0.f;

  const float* ipb = g_U1 + (size_t)b*64*4096;
  int r0 = tid/34, c0 = tid - r0*34;
  int r1 = (tid+256)/34, c1 = (tid+256) - r1*34;
  bool has1 = (tid+256) < 340;
  bool wact = tid < 64;
  float s0, s1 = 0.f;
  {
    int giy = yq0-1+r0, gix = xq0-1+c0;
    s0 = (giy>=0&&giy<64&&gix>=0&&gix<64)?__ldg(ipb+giy*64+gix):0.f;
    if (has1){
      int giy1 = yq0-1+r1, gix1 = xq0-1+c1;
      s1 = (giy1>=0&&giy1<64&&gix1>=0&&gix1<64)?__ldg(ipb+giy1*64+gix1):0.f;
    }
  }
  float wv0 = wact ? __ldg(g_TW_D3 + tid) : 0.f;
  int pb = 0;
  for (int ci=0; ci<64; ci++){
    sIn[pb][r0*40 + c0] = s0;
    if (has1) sIn[pb][r1*40 + c1] = s1;
    if (wact) sW[pb][tid] = wv0;
    __syncthreads();
    if (ci+1 < 64){
      const float* ip = ipb + (size_t)(ci+1)*4096;
      int giy = yq0-1+r0, gix = xq0-1+c0;
      s0 = (giy>=0&&giy<64&&gix>=0&&gix<64)?__ldg(ip+giy*64+gix):0.f;
      if (has1){
        int giy1 = yq0-1+r1, gix1 = xq0-1+c1;
        s1 = (giy1>=0&&giy1<64&&gix1>=0&&gix1<64)?__ldg(ip+giy1*64+gix1):0.f;
      }
      if (wact) wv0 = __ldg(g_TW_D3 + (size_t)(ci+1)*64 + tid);
    }
    float r3[3][3];
    #pragma unroll
    for (int dy=0;dy<3;dy++)
      #pragma unroll
      for (int dx=0;dx<3;dx++)
        r3[dy][dx] = sIn[pb][(ty+dy)*40 + tx+dx];
    #pragma unroll
    for (int ky=0;ky<4;ky++){
      #pragma unroll
      for (int kx=0;kx<4;kx++){
        float rv = r3[(4-ky)>>1][(4-kx)>>1];
        const int pp = (((ky&1)^1)<<1) | ((kx&1)^1);
        float4 wv = *reinterpret_cast<const float4*>(&sW[pb][(ky*4+kx)*4]);
        acc[0][pp]=fmaf(wv.x,rv,acc[0][pp]);
        acc[1][pp]=fmaf(wv.y,rv,acc[1][pp]);
        acc[2][pp]=fmaf(wv.z,rv,acc[2][pp]);
      }
    }
    pb ^= 1;
  }
  int yq = yq0 + ty, xq = xq0 + tx;
  #pragma unroll
  for (int j=0;j<3;j++){
    float bv = __ldg(bias+j);
    float* op = out + (size_t)(b*3+j)*16384;
    float2 e0 = make_float2(acc[j][0]+bv, acc[j][1]+bv);
    float2 e1 = make_float2(acc[j][2]+bv, acc[j][3]+bv);
    *reinterpret_cast<float2*>(op + (2*yq+0)*128 + 2*xq) = e0;
    *reinterpret_cast<float2*>(op + (2*yq+1)*128 + 2*xq) = e1;
  }
}

// ---------------- finalize: idx as float -------------------------------------
__global__ void k_final(float* __restrict__ out){
  int t = blockIdx.x*blockDim.x + threadIdx.x;
  if (t < 65536) out[3145730 + t] = (float)g_IDX[t];
}

// ---------------- loss: parallel deterministic double reduction --------------
__global__ void k_loss(float* __restrict__ out){
  __shared__ double sd[512];
  int t = threadIdx.x;
  sd[t] = g_PART[t];
  __syncthreads();
  #pragma unroll
  for (int s=256;s>0;s>>=1){
    if (t<s) sd[t] += sd[t+s];
    __syncthreads();
  }
  if (t==0){
    float m = (float)(sd[0] / 4194304.0);
    out[3145728] = m;   // codebook_loss
    out[3145729] = m;   // commitment_loss (identical value)
  }
}

// ---------------- launcher ---------------------------------------------------
extern "C" void kernel_launch(void* const* d_in, const int* in_sizes, int n_in,
                              void* d_out, int out_size)
{
  const float* patch=(const float*)d_in[0];
  const float* ew1=(const float*)d_in[1];  const float* eb1=(const float*)d_in[2];
  const float* ew2=(const float*)d_in[3];  const float* eb2=(const float*)d_in[4];
  const float* ew3=(const float*)d_in[5];  const float* eb3=(const float*)d_in[6];
  const float* er1a=(const float*)d_in[7]; const float* er1b=(const float*)d_in[8];
  const float* er2a=(const float*)d_in[9]; const float* er2b=(const float*)d_in[10];
  const float* pqw=(const float*)d_in[11]; const float* pqb=(const float*)d_in[12];
  const float* emb=(const float*)d_in[13];
  const float* dw1=(const float*)d_in[14]; const float* db1=(const float*)d_in[15];
  const float* dr1a=(const float*)d_in[16];const float* dr1b=(const float*)d_in[17];
  const float* dr2a=(const float*)d_in[18];const float* dr2b=(const float*)d_in[19];
  const float* dw2=(const float*)d_in[20]; const float* db2=(const float*)d_in[21];
  const float* dw3=(const float*)d_in[22]; const float* db3=(const float*)d_in[23];
  float* out = (float*)d_out;
  (void)in_sizes; (void)n_in; (void)out_size;

  // esq + all weight transposes in one kernel
  k_prep<<<2492,256>>>(emb, ew1, ew2, ew3, er1a, er2a, dr1a, dr2a, dw1, dw2, dw3);

  // encoder
  k_conv4s<3,64,128,16> <<<dim3(4,4,NB),256>>>(patch, -1, 10, eb1, 0);
  k_conv4s<64,128,64,8> <<<dim3(16,1,NB),256>>>(nullptr, 0, 11, eb2, 1);
  k_conv3s<128,128,8,false,false,true><<<dim3(16,NB),256>>>(1, 12, eb3, 2);
  // residual block 1
  k_conv3s<128,32,8,true,true,false><<<dim3(4,NB),256>>>(2, 13, nullptr, 3);
  k_res1x1v<<<dim3(4,NB),256>>>(3, er1b, 2);
  // residual block 2
  k_conv3s<128,32,8,true,true,false><<<dim3(4,NB),256>>>(2, 14, nullptr, 3);
  k_res1x1v<<<dim3(4,NB),256>>>(3, er2b, 2);
  // pre-quant (relu fused into input)
  k_pqv<<<dim3(4,NB),256>>>(2, pqw, pqb);
  // vector quantization
  k_vq<<<512,128>>>(emb);

  // decoder
  k_conv3s<64,128,8,false,false,true><<<dim3(16,NB),256>>>(5, 17, db1, 6);
  k_conv3s<128,32,8,true,true,false><<<dim3(4,NB),256>>>(6, 15, nullptr, 3);
  k_res1x1v<<<dim3(4,NB),256>>>(3, dr1b, 6);
  k_conv3s<128,32,8,true,true,false><<<dim3(4,NB),256>>>(6, 16, nullptr, 3);
  k_res1x1v<<<dim3(4,NB),256>>>(3, dr2b, 6);
  k_convT2s<<<dim3(4,4,NB),256>>>(db2);
  k_convT3s<<<dim3(2,8,NB),256>>>(db3, out);

  // losses + indices
  k_loss<<<1,512>>>(out);
  k_final<<<256,256>>>(out);
}

// round 17
// speedup vs baseline: 1.0746x; 1.0227x over previous
#include <cuda_runtime.h>
#include <cfloat>
#include <cstddef>

#define NB 64   // batch

typedef unsigned long long u64;

// ---- packed f32x2 helpers ---------------------------------------------------
__device__ __forceinline__ u64 pk2(float lo, float hi){
  u64 r; asm("mov.b64 %0,{%1,%2};" : "=l"(r) : "f"(lo), "f"(hi)); return r;
}
__device__ __forceinline__ float2 up2(u64 v){
  float2 f; asm("mov.b64 {%0,%1},%2;" : "=f"(f.x), "=f"(f.y) : "l"(v)); return f;
}
__device__ __forceinline__ void fma2(u64 &d, u64 a, u64 b){
  asm("fma.rn.f32x2 %0,%1,%2,%0;" : "+l"(d) : "l"(a), "l"(b));
}

// ---------------- scratch buffers (device globals; no allocations) ----------
__device__ __align__(16) float g_A1[(size_t)NB*64*64*64];   // enc conv1 out
__device__ __align__(16) float g_A2[(size_t)NB*128*32*32];  // enc conv2 out
__device__ __align__(16) float g_A3[(size_t)NB*128*32*32];  // enc conv3/res
__device__ __align__(16) float g_T [(size_t)NB*32*32*32];   // res 3x3 temp
__device__ __align__(16) float g_Z [(size_t)NB*32*32*64];   // z NHWC
__device__ __align__(16) float g_ZQ[(size_t)NB*64*32*32];   // z_q NCHW
__device__ __align__(16) float g_D1[(size_t)NB*128*32*32];  // dec trunk
__device__ __align__(16) float g_U1[(size_t)NB*64*64*64];   // dec upsample
// pre-transposed weights: [ci][tap][co]
__device__ __align__(16) float g_TW_E1[3*16*64];
__device__ __align__(16) float g_TW_E2[64*16*128];
__device__ __align__(16) float g_TW_E3[128*9*128];
__device__ __align__(16) float g_TW_R1A[128*9*32];
__device__ __align__(16) float g_TW_R2A[128*9*32];
__device__ __align__(16) float g_TW_DR1A[128*9*32];
__device__ __align__(16) float g_TW_DR2A[128*9*32];
__device__ __align__(16) float g_TW_DEC[64*9*128];          // flipped dw1
__device__ __align__(16) float g_TW_D2[128*16*64];
__device__ __align__(16) float g_TW_D3[64*16*4];            // co padded 3->4
__device__ float  g_ESQ[1024];
__device__ int    g_IDX[65536];
__device__ double g_PART[512];

__device__ __forceinline__ float* gbuf(int id){
  switch(id){
    case 0: return g_A1; case 1: return g_A2; case 2: return g_A3;
    case 3: return g_T;  case 4: return g_Z;  case 5: return g_ZQ;
    case 6: return g_D1; case 7: return g_U1;
    case 10: return g_TW_E1;  case 11: return g_TW_E2;  case 12: return g_TW_E3;
    case 13: return g_TW_R1A; case 14: return g_TW_R2A; case 15: return g_TW_DR1A;
    case 16: return g_TW_DR2A;case 17: return g_TW_DEC; case 18: return g_TW_D2;
    default: return g_TW_D3;
  }
}
__device__ __forceinline__ const float* gbuf_c(int id, const float* ext){
  if (id < 0) return ext;
  return gbuf(id);
}

// ---------------- merged prep: esq + all weight transposes -------------------
__device__ __forceinline__ void trA_i(const float* __restrict__ w, float* T,
                                      int CI,int CO,int KK,int t){
  int co = t/(CI*KK); int r = t%(CI*KK); int ci = r/KK, kk = r%KK;
  T[((size_t)ci*KK+kk)*CO+co] = w[t];
}
__device__ __forceinline__ void trB_i(const float* __restrict__ w, float* T,
                                      int CI,int CO,int KK,int COP,int t){
  int ci = t/(CO*KK); int r = t%(CO*KK); int co = r/KK, kk = r%KK;
  T[((size_t)ci*KK+kk)*COP+co] = w[t];
}

__global__ void k_prep(const float* __restrict__ emb,
                       const float* __restrict__ ew1, const float* __restrict__ ew2,
                       const float* __restrict__ ew3,
                       const float* __restrict__ er1a, const float* __restrict__ er2a,
                       const float* __restrict__ dr1a, const float* __restrict__ dr2a,
                       const float* __restrict__ dw1, const float* __restrict__ dw2,
                       const float* __restrict__ dw3)
{
  int t = blockIdx.x*256 + threadIdx.x;
  if (t < 1024){
    const float4* e = reinterpret_cast<const float4*>(emb + (size_t)t*64);
    float s = 0.f;
    #pragma unroll
    for (int i=0;i<16;i++){
      float4 v = e[i];
      s = fmaf(v.x,v.x,fmaf(v.y,v.y,fmaf(v.z,v.z,fmaf(v.w,v.w,s))));
    }
    g_ESQ[t] = s; return;
  } t -= 1024;
  if (t < 3072){ trA_i(ew1, g_TW_E1, 3,64,16, t); return; } t -= 3072;
  if (t < 131072){ trA_i(ew2, g_TW_E2, 64,128,16, t); return; } t -= 131072;
  if (t < 147456){ trA_i(ew3, g_TW_E3, 128,128,9, t); return; } t -= 147456;
  if (t < 36864){ trA_i(er1a, g_TW_R1A, 128,32,9, t); return; } t -= 36864;
  if (t < 36864){ trA_i(er2a, g_TW_R2A, 128,32,9, t); return; } t -= 36864;
  if (t < 36864){ trA_i(dr1a, g_TW_DR1A, 128,32,9, t); return; } t -= 36864;
  if (t < 36864){ trA_i(dr2a, g_TW_DR2A, 128,32,9, t); return; } t -= 36864;
  if (t < 73728){
    int ci = t/(128*9); int r = t%(128*9); int co = r/9, kk = r%9;
    int ky = kk/3, kx = kk%3;
    g_TW_DEC[((size_t)ci*9 + (2-ky)*3 + (2-kx))*128 + co] = dw1[t]; return;
  } t -= 73728;
  if (t < 131072){ trB_i(dw2, g_TW_D2, 128,64,16,64, t); return; } t -= 131072;
  if (t < 3072){ trB_i(dw3, g_TW_D3, 64,3,16,4, t); }
}

// ---------------- 3x3 s1 p1 conv at 32x32, f32x2, 4-ci stages ----------------
template<int CIN,int COUT,int COT,bool RIN,bool ROUT,bool HASB>
__global__ void __launch_bounds__(256,3)
k_conv3s(int in_id, int w_id, const float* __restrict__ bias, int out_id)
{
  constexpr int CP   = COT/2;
  constexpr int WSZ  = 9*COT;        // weight floats per plane (72 for COT=8)
  constexpr int WTOT = 4*WSZ;        // 288 for COT=8
  static_assert(WTOT <= 512, "weight staging assumes <=2 elements per thread");
  static_assert(CIN % 4 == 0, "quad ci staging");
  __shared__ __align__(16) float sIn[2][4][34*40];
  __shared__ __align__(16) float sW [2][WTOT];
  const float* in = gbuf_c(in_id, nullptr);
  const float* W  = gbuf_c(w_id, nullptr);
  float* out = gbuf(out_id);
  int co0 = blockIdx.x*COT;
  int b   = blockIdx.y;
  int tid = threadIdx.x;
  int tx = tid & 7, ty = tid >> 3;
  int x0 = tx*4;

  for (int i=tid; i<34*40; i+=256){
    #pragma unroll
    for (int pl=0; pl<4; pl++){ sIn[0][pl][i]=0.f; sIn[1][pl][i]=0.f; }
  }
  __syncthreads();

  u64 acc[CP][4];
  #pragma unroll
  for (int j=0;j<CP;j++){
    u64 bp = HASB ? pk2(__ldg(bias+co0+2*j), __ldg(bias+co0+2*j+1)) : 0ull;
    #pragma unroll
    for (int p=0;p<4;p++) acc[j][p] = bp;
  }

  const float* ipb = in + (size_t)b*CIN*1024;
  // weight staging: element e -> pl=e/WSZ, tap=(e%WSZ)/COT, co=(e%WSZ)%COT
  // thread stages e = tid and (if tid < WTOT-256) e = 256+tid
  bool wact2 = tid < (WTOT-256);
  int e0pl = tid / WSZ, e0r = tid % WSZ;
  int e1 = 256 + tid;
  int e1pl = e1 / WSZ, e1r = e1 % WSZ;
  const float* wb0 = W + ((size_t)e0pl*9 + e0r/COT)*COUT + co0 + (e0r%COT);
  const float* wb1 = W + ((size_t)e1pl*9 + e1r/COT)*COUT + co0 + (e1r%COT);

  float4 va = __ldg(reinterpret_cast<const float4*>(ipb) + tid);
  float4 vc = __ldg(reinterpret_cast<const float4*>(ipb + 1024) + tid);
  float4 vd = __ldg(reinterpret_cast<const float4*>(ipb + 2048) + tid);
  float4 ve = __ldg(reinterpret_cast<const float4*>(ipb + 3072) + tid);
  if (RIN){
    va.x=fmaxf(va.x,0.f); va.y=fmaxf(va.y,0.f); va.z=fmaxf(va.z,0.f); va.w=fmaxf(va.w,0.f);
    vc.x=fmaxf(vc.x,0.f); vc.y=fmaxf(vc.y,0.f); vc.z=fmaxf(vc.z,0.f); vc.w=fmaxf(vc.w,0.f);
    vd.x=fmaxf(vd.x,0.f); vd.y=fmaxf(vd.y,0.f); vd.z=fmaxf(vd.z,0.f); vd.w=fmaxf(vd.w,0.f);
    ve.x=fmaxf(ve.x,0.f); ve.y=fmaxf(ve.y,0.f); ve.z=fmaxf(ve.z,0.f); ve.w=fmaxf(ve.w,0.f);
  }
  float wv0 = __ldg(wb0);
  float wv1 = wact2 ? __ldg(wb1) : 0.f;

  int sb = (ty+1)*40 + 1 + x0;
  int pb = 0;
  for (int ci=0; ci<CIN; ci+=4){
    { float* sp=&sIn[pb][0][sb]; sp[0]=va.x; sp[1]=va.y; sp[2]=va.z; sp[3]=va.w; }
    { float* sp=&sIn[pb][1][sb]; sp[0]=vc.x; sp[1]=vc.y; sp[2]=vc.z; sp[3]=vc.w; }
    { float* sp=&sIn[pb][2][sb]; sp[0]=vd.x; sp[1]=vd.y; sp[2]=vd.z; sp[3]=vd.w; }
    { float* sp=&sIn[pb][3][sb]; sp[0]=ve.x; sp[1]=ve.y; sp[2]=ve.z; sp[3]=ve.w; }
    sW[pb][tid] = wv0;
    if (wact2) sW[pb][256+tid] = wv1;
    __syncthreads();
    if (ci+4 < CIN){
      va = __ldg(reinterpret_cast<const float4*>(ipb + (size_t)(ci+4)*1024) + tid);
      vc = __ldg(reinterpret_cast<const float4*>(ipb + (size_t)(ci+5)*1024) + tid);
      vd = __ldg(reinterpret_cast<const float4*>(ipb + (size_t)(ci+6)*1024) + tid);
      ve = __ldg(reinterpret_cast<const float4*>(ipb + (size_t)(ci+7)*1024) + tid);
      if (RIN){
        va.x=fmaxf(va.x,0.f); va.y=fmaxf(va.y,0.f); va.z=fmaxf(va.z,0.f); va.w=fmaxf(va.w,0.f);
        vc.x=fmaxf(vc.x,0.f); vc.y=fmaxf(vc.y,0.f); vc.z=fmaxf(vc.z,0.f); vc.w=fmaxf(vc.w,0.f);
        vd.x=fmaxf(vd.x,0.f); vd.y=fmaxf(vd.y,0.f); vd.z=fmaxf(vd.z,0.f); vd.w=fmaxf(vd.w,0.f);
        ve.x=fmaxf(ve.x,0.f); ve.y=fmaxf(ve.y,0.f); ve.z=fmaxf(ve.z,0.f); ve.w=fmaxf(ve.w,0.f);
      }
      wv0 = __ldg(wb0 + (size_t)(ci+4)*9*COUT);
      if (wact2) wv1 = __ldg(wb1 + (size_t)(ci+4)*9*COUT);
    }
    #pragma unroll
    for (int pl=0; pl<4; pl++){
      #pragma unroll
      for (int ky=0;ky<3;ky++){
        const float* row = &sIn[pb][pl][(ty+ky)*40 + x0];
        float4 a = *reinterpret_cast<const float4*>(row);
        float2 e45 = *reinterpret_cast<const float2*>(row+4);   // aligned LDS.64
        u64 vb[6];
        vb[0]=pk2(a.x,a.x); vb[1]=pk2(a.y,a.y); vb[2]=pk2(a.z,a.z);
        vb[3]=pk2(a.w,a.w); vb[4]=pk2(e45.x,e45.x); vb[5]=pk2(e45.y,e45.y);
        #pragma unroll
        for (int kx=0;kx<3;kx++){
          const ulonglong2* wq = reinterpret_cast<const ulonglong2*>(&sW[pb][pl*WSZ + (ky*3+kx)*COT]);
          #pragma unroll
          for (int j2=0;j2<CP/2;j2++){
            ulonglong2 wv = wq[j2];
            #pragma unroll
            for (int p=0;p<4;p++){
              fma2(acc[2*j2  ][p], wv.x, vb[kx+p]);
              fma2(acc[2*j2+1][p], wv.y, vb[kx+p]);
            }
          }
        }
      }
    }
    pb ^= 1;
  }
  #pragma unroll
  for (int j=0;j<CP;j++){
    float2 f0=up2(acc[j][0]), f1=up2(acc[j][1]), f2=up2(acc[j][2]), f3=up2(acc[j][3]);
    float4 oe = make_float4(f0.x,f1.x,f2.x,f3.x);
    float4 oo = make_float4(f0.y,f1.y,f2.y,f3.y);
    if (ROUT){
      oe.x=fmaxf(oe.x,0.f); oe.y=fmaxf(oe.y,0.f); oe.z=fmaxf(oe.z,0.f); oe.w=fmaxf(oe.w,0.f);
      oo.x=fmaxf(oo.x,0.f); oo.y=fmaxf(oo.y,0.f); oo.z=fmaxf(oo.z,0.f); oo.w=fmaxf(oo.w,0.f);
    }
    *reinterpret_cast<float4*>(out + ((size_t)(b*COUT+co0+2*j  )*32 + ty)*32 + x0) = oe;
    *reinterpret_cast<float4*>(out + ((size_t)(b*COUT+co0+2*j+1)*32 + ty)*32 + x0) = oo;
  }
}

// ---------------- 4x4 s2 p1 conv, f32x2, dbl-buf input+weights ---------------
template<int CIN,int COUT,int HIN,int COT>
__global__ void __launch_bounds__(256,2)
k_conv4s(const float* __restrict__ ext_in, int in_id, int w_id,
         const float* __restrict__ bias, int out_id)
{
  constexpr int CP = COT/2;
  constexpr int HOUT = HIN/2;
  constexpr int XT   = HOUT/32;
  constexpr int WSZ  = 16*COT;
  static_assert(WSZ <= 256, "weight staging assumes one element per thread");
  __shared__ __align__(16) float sIn[2][66*72];
  __shared__ __align__(16) float sW [2][WSZ];
  const float* in = gbuf_c(in_id, ext_in);
  const float* W  = gbuf_c(w_id, nullptr);
  float* out = gbuf(out_id);
  int co0 = blockIdx.x*COT;
  int oy0 = (blockIdx.y/XT)*32, ox0 = (blockIdx.y%XT)*32;
  int b = blockIdx.z;
  int tid = threadIdx.x;
  int tx = tid & 7, ty = tid >> 3;
  int x0 = tx*4;

  u64 acc[CP][4];
  #pragma unroll
  for (int j=0;j<CP;j++){
    u64 bp = pk2(__ldg(bias+co0+2*j), __ldg(bias+co0+2*j+1));
    #pragma unroll
    for (int p=0;p<4;p++) acc[j][p] = bp;
  }

  int iy0 = oy0*2 - 1, ix0 = ox0*2 - 1;
  int wk = tid / COT, wj = tid % COT;
  bool wact = tid < WSZ;
  const float* wsrc0 = W + (size_t)wk*COUT + co0 + wj;

  float sreg[18];
  {
    const float* ip = in + (size_t)b*CIN*HIN*HIN;
    #pragma unroll
    for (int t=0;t<18;t++){
      int s = tid + t*256; float v = 0.f;
      if (s < 4356){
        int r = s/66, c = s - r*66;
        int giy = iy0 + r, gix = ix0 + c;
        if (giy>=0 && giy<HIN && gix>=0 && gix<HIN) v = __ldg(ip + (size_t)giy*HIN + gix);
      }
      sreg[t] = v;
    }
  }
  float wv0 = wact ? __ldg(wsrc0) : 0.f;

  int pb = 0;
  for (int ci=0; ci<CIN; ci++){
    #pragma unroll
    for (int t=0;t<18;t++){
      int s = tid + t*256;
      if (s < 4356){ int r = s/66, c = s - r*66; sIn[pb][r*72 + c] = sreg[t]; }
    }
    if (wact) sW[pb][tid] = wv0;
    __syncthreads();
    if (ci+1 < CIN){
      const float* ip = in + (size_t)(b*CIN+ci+1)*HIN*HIN;
      #pragma unroll
      for (int t=0;t<18;t++){
        int s = tid + t*256; float v = 0.f;
        if (s < 4356){
          int r = s/66, c = s - r*66;
          int giy = iy0 + r, gix = ix0 + c;
          if (giy>=0 && giy<HIN && gix>=0 && gix<HIN) v = __ldg(ip + (size_t)giy*HIN + gix);
        }
        sreg[t] = v;
      }
      if (wact) wv0 = __ldg(wsrc0 + (size_t)(ci+1)*16*COUT);
    }
    #pragma unroll
    for (int ky=0;ky<4;ky++){
      const float* row = &sIn[pb][(2*ty+ky)*72 + 2*x0];
      float4 a  = *reinterpret_cast<const float4*>(row);
      float4 bq = *reinterpret_cast<const float4*>(row+4);
      float2 e89 = *reinterpret_cast<const float2*>(row+8);
      u64 vb[10];
      vb[0]=pk2(a.x,a.x); vb[1]=pk2(a.y,a.y); vb[2]=pk2(a.z,a.z); vb[3]=pk2(a.w,a.w);
      vb[4]=pk2(bq.x,bq.x); vb[5]=pk2(bq.y,bq.y); vb[6]=pk2(bq.z,bq.z); vb[7]=pk2(bq.w,bq.w);
      vb[8]=pk2(e89.x,e89.x); vb[9]=pk2(e89.y,e89.y);
      #pragma unroll
      for (int kx=0;kx<4;kx++){
        const ulonglong2* wq = reinterpret_cast<const ulonglong2*>(&sW[pb][(ky*4+kx)*COT]);
        #pragma unroll
        for (int j2=0;j2<CP/2;j2++){
          ulonglong2 wv = wq[j2];
          #pragma unroll
          for (int p=0;p<4;p++){
            fma2(acc[2*j2  ][p], wv.x, vb[kx+2*p]);
            fma2(acc[2*j2+1][p], wv.y, vb[kx+2*p]);
          }
        }
      }
    }
    pb ^= 1;
  }
  #pragma unroll
  for (int j=0;j<CP;j++){
    float2 f0=up2(acc[j][0]), f1=up2(acc[j][1]), f2=up2(acc[j][2]), f3=up2(acc[j][3]);
    float4 oe = make_float4(fmaxf(f0.x,0.f),fmaxf(f1.x,0.f),fmaxf(f2.x,0.f),fmaxf(f3.x,0.f));
    float4 oo = make_float4(fmaxf(f0.y,0.f),fmaxf(f1.y,0.f),fmaxf(f2.y,0.f),fmaxf(f3.y,0.f));
    *reinterpret_cast<float4*>(out + ((size_t)(b*COUT+co0+2*j  )*HOUT + oy0+ty)*HOUT + ox0+x0) = oe;
    *reinterpret_cast<float4*>(out + ((size_t)(b*COUT+co0+2*j+1)*HOUT + oy0+ty)*HOUT + ox0+x0) = oo;
  }
}

// ---------------- 1x1 conv residual-add, f32x2 over co pairs -----------------
__global__ void __launch_bounds__(256)
k_res1x1v(int t_id, const float* __restrict__ w, int x_id)
{
  __shared__ __align__(16) u64 swp[64*32];   // [co2][ci] packed (co, co+1) pairs
  const float* t = gbuf_c(t_id, nullptr);
  float* x = gbuf(x_id);
  int b = blockIdx.y, p = blockIdx.x*256 + threadIdx.x;
  for (int i=threadIdx.x; i<2048; i+=256){
    int co2 = i >> 5, ci = i & 31;
    swp[i] = pk2(__ldg(w + (size_t)(2*co2)*32 + ci),
                 __ldg(w + (size_t)(2*co2+1)*32 + ci));
  }
  __syncthreads();
  u64 rvp[32];
  #pragma unroll
  for (int ci=0;ci<32;ci++){
    float v = __ldg(t + (size_t)(b*32+ci)*1024 + p);
    rvp[ci] = pk2(v,v);
  }
  #pragma unroll 2
  for (int co2=0;co2<64;co2++){
    u64 a = 0ull;
    const u64* wr = &swp[co2*32];
    #pragma unroll
    for (int ci=0;ci<32;ci++) fma2(a, wr[ci], rvp[ci]);
    float2 f = up2(a);
    x[(size_t)(b*128+2*co2  )*1024 + p] += f.x;
    x[(size_t)(b*128+2*co2+1)*1024 + p] += f.y;
  }
}

// ---------------- pre-quant 1x1: relu(in) -> z NHWC, f32x2 over d pairs ------
__global__ void __launch_bounds__(256)
k_pqv(int in_id, const float* __restrict__ w, const float* __restrict__ bias)
{
  __shared__ __align__(16) u64 swp[128*32];  // [ci][d2] packed (d, d+1) pairs
  const float* h = gbuf_c(in_id, nullptr);
  int b = blockIdx.y, p = blockIdx.x*256 + threadIdx.x;
  for (int i=threadIdx.x; i<4096; i+=256){
    int ci = i >> 5, d2 = i & 31;
    swp[i] = pk2(__ldg(w + (size_t)(2*d2)*128 + ci),
                 __ldg(w + (size_t)(2*d2+1)*128 + ci));
  }
  __syncthreads();
  u64 acc2[32];
  #pragma unroll
  for (int d2=0;d2<32;d2++) acc2[d2] = pk2(__ldg(bias+2*d2), __ldg(bias+2*d2+1));
  const float* ip = h + (size_t)b*128*1024 + p;
  for (int ci=0;ci<128;ci++){
    float v = fmaxf(__ldg(ip + (size_t)ci*1024), 0.f);
    u64 vp = pk2(v,v);
    const u64* wr = &swp[ci*32];
    #pragma unroll
    for (int d2=0;d2<32;d2++) fma2(acc2[d2], wr[d2], vp);
  }
  float4* zp = reinterpret_cast<float4*>(g_Z + (size_t)(b*1024+p)*64);
  #pragma unroll
  for (int q=0;q<16;q++){
    float2 f0 = up2(acc2[2*q]), f1 = up2(acc2[2*q+1]);
    zp[q] = make_float4(f0.x, f0.y, f1.x, f1.y);
  }
}

// ---------------- VQ: argmin via f32x2 (bit-identical chains) ----------------
__global__ void k_vq(const float* __restrict__ emb){
  __shared__ __align__(16) float sE[128*64];
  __shared__ float sQ[128];
  __shared__ double sred[128];
  int tid = threadIdx.x;
  int n = blockIdx.x*128 + tid;
  int b = n >> 10, p = n & 1023;
  __align__(16) float zr[64];
  {
    const float4* zp = reinterpret_cast<const float4*>(g_Z + (size_t)n*64);
    float4* zr4 = reinterpret_cast<float4*>(zr);
    #pragma unroll
    for (int i=0;i<16;i++) zr4[i] = zp[i];
  }
  const u64* z2 = reinterpret_cast<const u64*>(zr);
  float best = FLT_MAX; int bi = 0;
  for (int c=0;c<8;c++){
    const float4* src = reinterpret_cast<const float4*>(emb) + (size_t)c*2048;
    float4* dst = reinterpret_cast<float4*>(sE);
    #pragma unroll
    for (int r=0;r<16;r++) dst[tid + r*128] = src[tid + r*128];
    sQ[tid] = g_ESQ[c*128+tid];
    __syncthreads();
    for (int kk=0;kk<128;kk++){
      const ulonglong2* e2 = reinterpret_cast<const ulonglong2*>(sE + kk*64);
      u64 p01 = 0ull, p23 = 0ull;
      #pragma unroll
      for (int i=0;i<16;i++){
        ulonglong2 ev = e2[i];
        fma2(p01, ev.x, z2[2*i]);
        fma2(p23, ev.y, z2[2*i+1]);
      }
      float2 f01 = up2(p01), f23 = up2(p23);
      float sc = sQ[kk] - 2.f*((f01.x+f01.y)+(f23.x+f23.y));
      if (sc < best){ best = sc; bi = c*128+kk; }   // strict < : first min
    }
    __syncthreads();
  }
  g_IDX[n] = bi;
  const float* er = emb + (size_t)bi*64;
  float ls = 0.f;
  #pragma unroll
  for (int d=0; d<64; d++){
    float e = __ldg(er+d);
    g_ZQ[(size_t)(b*64+d)*1024 + p] = e;
    float df = e - zr[d];
    ls = fmaf(df,df,ls);
  }
  sred[tid] = (double)ls;
  __syncthreads();
  #pragma unroll
  for (int s=64;s>0;s>>=1){
    if (tid<s) sred[tid] += sred[tid+s];
    __syncthreads();
  }
  if (tid==0) g_PART[blockIdx.x] = sred[0];
}

// ---------------- ConvTranspose 4x4 s2 p1: 128@32 -> 64@64, 2-ci stages ------
// COT=16: launch with gridDim.x == 4
__global__ void __launch_bounds__(256,2)
k_convT2s(const float* __restrict__ bias)
{
  constexpr int CP = 8;
  __shared__ __align__(16) float sIn[2][2][400];
  __shared__ __align__(16) float sW [2][512];
  int co0 = blockIdx.x*16;
  int yq0 = blockIdx.y*8;
  int b   = blockIdx.z;
  int tid = threadIdx.x;
  int tx = tid & 31, ty = tid >> 5;

  u64 acc[CP][4];
  #pragma unroll
  for (int j=0;j<CP;j++)
    #pragma unroll
    for (int q=0;q<4;q++) acc[j][q] = 0ull;

  const float* ipb = g_D1 + (size_t)b*128*1024;
  int r0 = tid/34, c0 = tid - r0*34;
  int r1 = (tid+256)/34, c1 = (tid+256) - r1*34;
  bool has1 = (tid+256) < 340;
  int giy0 = yq0-1+r0, gix0 = c0-1;
  int giy1 = yq0-1+r1, gix1 = c1-1;
  bool in0 = (giy0>=0 && giy0<32 && gix0>=0 && gix0<32);
  bool in1 = has1 && (giy1>=0 && giy1<32 && gix1>=0 && gix1<32);
  int off0 = giy0*32+gix0, off1 = giy1*32+gix1;
  const float* wsrc = g_TW_D2 + (size_t)(tid>>4)*64 + co0 + (tid&15);

  float a0,a1,b0v,b1v;
  a0  = in0 ? fmaxf(__ldg(ipb + off0),0.f) : 0.f;
  a1  = in1 ? fmaxf(__ldg(ipb + off1),0.f) : 0.f;
  b0v = in0 ? fmaxf(__ldg(ipb + 1024 + off0),0.f) : 0.f;
  b1v = in1 ? fmaxf(__ldg(ipb + 1024 + off1),0.f) : 0.f;
  float wa = __ldg(wsrc);
  float wb = __ldg(wsrc + 1024);

  int pb = 0;
  for (int ci=0; ci<128; ci+=2){
    sIn[pb][0][r0*40 + c0] = a0;
    if (has1) sIn[pb][0][r1*40 + c1] = a1;
    sIn[pb][1][r0*40 + c0] = b0v;
    if (has1) sIn[pb][1][r1*40 + c1] = b1v;
    sW[pb][tid] = wa;
    sW[pb][256+tid] = wb;
    __syncthreads();
    if (ci+2 < 128){
      const float* ip0 = ipb + (size_t)(ci+2)*1024;
      const float* ip1 = ipb + (size_t)(ci+3)*1024;
      a0  = in0 ? fmaxf(__ldg(ip0 + off0),0.f) : 0.f;
      a1  = in1 ? fmaxf(__ldg(ip0 + off1),0.f) : 0.f;
      b0v = in0 ? fmaxf(__ldg(ip1 + off0),0.f) : 0.f;
      b1v = in1 ? fmaxf(__ldg(ip1 + off1),0.f) : 0.f;
      wa = __ldg(wsrc + (size_t)(ci+2)*1024);
      wb = __ldg(wsrc + (size_t)(ci+3)*1024);
    }
    #pragma unroll
    for (int pl=0; pl<2; pl++){
      u64 rp[9];
      #pragma unroll
      for (int dy=0;dy<3;dy++)
        #pragma unroll
        for (int dx=0;dx<3;dx++){
          float rv = sIn[pb][pl][(ty+dy)*40 + tx+dx];
          rp[dy*3+dx] = pk2(rv,rv);
        }
      #pragma unroll
      for (int ky=0;ky<4;ky++){
        #pragma unroll
        for (int kx=0;kx<4;kx++){
          u64 rv = rp[((4-ky)>>1)*3 + ((4-kx)>>1)];
          const int pp = (((ky&1)^1)<<1) | ((kx&1)^1);
          const ulonglong2* wq = reinterpret_cast<const ulonglong2*>(&sW[pb][pl*256 + (ky*4+kx)*16]);
          #pragma unroll
          for (int j2=0;j2<CP/2;j2++){
            ulonglong2 wv = wq[j2];
            fma2(acc[2*j2  ][pp], wv.x, rv);
            fma2(acc[2*j2+1][pp], wv.y, rv);
          }
        }
      }
    }
    pb ^= 1;
  }
  int yq = yq0 + ty;
  #pragma unroll
  for (int j=0;j<CP;j++){
    float2 f0=up2(acc[j][0]), f1=up2(acc[j][1]), f2=up2(acc[j][2]), f3=up2(acc[j][3]);
    float bvx = __ldg(bias+co0+2*j), bvy = __ldg(bias+co0+2*j+1);
    float* opx = g_U1 + (size_t)(b*64+co0+2*j)*4096;
    float* opy = g_U1 + (size_t)(b*64+co0+2*j+1)*4096;
    float2 ex0 = make_float2(fmaxf(f0.x+bvx,0.f), fmaxf(f1.x+bvx,0.f));
    float2 ex1 = make_float2(fmaxf(f2.x+bvx,0.f), fmaxf(f3.x+bvx,0.f));
    float2 ey0 = make_float2(fmaxf(f0.y+bvy,0.f), fmaxf(f1.y+bvy,0.f));
    float2 ey1 = make_float2(fmaxf(f2.y+bvy,0.f), fmaxf(f3.y+bvy,0.f));
    *reinterpret_cast<float2*>(opx + (2*yq+0)*64 + 2*tx) = ex0;
    *reinterpret_cast<float2*>(opx + (2*yq+1)*64 + 2*tx) = ex1;
    *reinterpret_cast<float2*>(opy + (2*yq+0)*64 + 2*tx) = ey0;
    *reinterpret_cast<float2*>(opy + (2*yq+1)*64 + 2*tx) = ey1;
  }
}

// ---------------- ConvTranspose 4x4 s2 p1: 64@64 -> 3@128 (recon) ------------
__global__ void __launch_bounds__(256,2)
k_convT3s(const float* __restrict__ bias, float* __restrict__ out)
{
  __shared__ __align__(16) float sIn[2][10*40];
  __shared__ __align__(16) float sW [2][64];
  int xq0 = blockIdx.x*32;
  int yq0 = blockIdx.y*8;
  int b   = blockIdx.z;
  int tid = threadIdx.x;
  int tx = tid & 31, ty = tid >> 5;

  float acc[3][4];
  #pragma unroll
  for (int j=0;j<3;j++)
    #pragma unroll
    for (int q=0;q<4;q++) acc[j][q]=0.f;

  const float* ipb = g_U1 + (size_t)b*64*4096;
  int r0 = tid/34, c0 = tid - r0*34;
  int r1 = (tid+256)/34, c1 = (tid+256) - r1*34;
  bool has1 = (tid+256) < 340;
  bool wact = tid < 64;
  float s0, s1 = 0.f;
  {
    int giy = yq0-1+r0, gix = xq0-1+c0;
    s0 = (giy>=0&&giy<64&&gix>=0&&gix<64)?__ldg(ipb+giy*64+gix):0.f;
    if (has1){
      int giy1 = yq0-1+r1, gix1 = xq0-1+c1;
      s1 = (giy1>=0&&giy1<64&&gix1>=0&&gix1<64)?__ldg(ipb+giy1*64+gix1):0.f;
    }
  }
  float wv0 = wact ? __ldg(g_TW_D3 + tid) : 0.f;
  int pb = 0;
  for (int ci=0; ci<64; ci++){
    sIn[pb][r0*40 + c0] = s0;
    if (has1) sIn[pb][r1*40 + c1] = s1;
    if (wact) sW[pb][tid] = wv0;
    __syncthreads();
    if (ci+1 < 64){
      const float* ip = ipb + (size_t)(ci+1)*4096;
      int giy = yq0-1+r0, gix = xq0-1+c0;
      s0 = (giy>=0&&giy<64&&gix>=0&&gix<64)?__ldg(ip+giy*64+gix):0.f;
      if (has1){
        int giy1 = yq0-1+r1, gix1 = xq0-1+c1;
        s1 = (giy1>=0&&giy1<64&&gix1>=0&&gix1<64)?__ldg(ip+giy1*64+gix1):0.f;
      }
      if (wact) wv0 = __ldg(g_TW_D3 + (size_t)(ci+1)*64 + tid);
    }
    float r3[3][3];
    #pragma unroll
    for (int dy=0;dy<3;dy++)
      #pragma unroll
      for (int dx=0;dx<3;dx++)
        r3[dy][dx] = sIn[pb][(ty+dy)*40 + tx+dx];
    #pragma unroll
    for (int ky=0;ky<4;ky++){
      #pragma unroll
      for (int kx=0;kx<4;kx++){
        float rv = r3[(4-ky)>>1][(4-kx)>>1];
        const int pp = (((ky&1)^1)<<1) | ((kx&1)^1);
        float4 wv = *reinterpret_cast<const float4*>(&sW[pb][(ky*4+kx)*4]);
        acc[0][pp]=fmaf(wv.x,rv,acc[0][pp]);
        acc[1][pp]=fmaf(wv.y,rv,acc[1][pp]);
        acc[2][pp]=fmaf(wv.z,rv,acc[2][pp]);
      }
    }
    pb ^= 1;
  }
  int yq = yq0 + ty, xq = xq0 + tx;
  #pragma unroll
  for (int j=0;j<3;j++){
    float bv = __ldg(bias+j);
    float* op = out + (size_t)(b*3+j)*16384;
    float2 e0 = make_float2(acc[j][0]+bv, acc[j][1]+bv);
    float2 e1 = make_float2(acc[j][2]+bv, acc[j][3]+bv);
    *reinterpret_cast<float2*>(op + (2*yq+0)*128 + 2*xq) = e0;
    *reinterpret_cast<float2*>(op + (2*yq+1)*128 + 2*xq) = e1;
  }
}

// ---------------- finalize: idx as float -------------------------------------
__global__ void k_final(float* __restrict__ out){
  int t = blockIdx.x*blockDim.x + threadIdx.x;
  if (t < 65536) out[3145730 + t] = (float)g_IDX[t];
}

// ---------------- loss: parallel deterministic double reduction --------------
__global__ void k_loss(float* __restrict__ out){
  __shared__ double sd[512];
  int t = threadIdx.x;
  sd[t] = g_PART[t];
  __syncthreads();
  #pragma unroll
  for (int s=256;s>0;s>>=1){
    if (t<s) sd[t] += sd[t+s];
    __syncthreads();
  }
  if (t==0){
    float m = (float)(sd[0] / 4194304.0);
    out[3145728] = m;   // codebook_loss
    out[3145729] = m;   // commitment_loss (identical value)
  }
}

// ---------------- launcher ---------------------------------------------------
extern "C" void kernel_launch(void* const* d_in, const int* in_sizes, int n_in,
                              void* d_out, int out_size)
{
  const float* patch=(const float*)d_in[0];
  const float* ew1=(const float*)d_in[1];  const float* eb1=(const float*)d_in[2];
  const float* ew2=(const float*)d_in[3];  const float* eb2=(const float*)d_in[4];
  const float* ew3=(const float*)d_in[5];  const float* eb3=(const float*)d_in[6];
  const float* er1a=(const float*)d_in[7]; const float* er1b=(const float*)d_in[8];
  const float* er2a=(const float*)d_in[9]; const float* er2b=(const float*)d_in[10];
  const float* pqw=(const float*)d_in[11]; const float* pqb=(const float*)d_in[12];
  const float* emb=(const float*)d_in[13];
  const float* dw1=(const float*)d_in[14]; const float* db1=(const float*)d_in[15];
  const float* dr1a=(const float*)d_in[16];const float* dr1b=(const float*)d_in[17];
  const float* dr2a=(const float*)d_in[18];const float* dr2b=(const float*)d_in[19];
  const float* dw2=(const float*)d_in[20]; const float* db2=(const float*)d_in[21];
  const float* dw3=(const float*)d_in[22]; const float* db3=(const float*)d_in[23];
  float* out = (float*)d_out;
  (void)in_sizes; (void)n_in; (void)out_size;

  // esq + all weight transposes in one kernel
  k_prep<<<2492,256>>>(emb, ew1, ew2, ew3, er1a, er2a, dr1a, dr2a, dw1, dw2, dw3);

  // encoder
  k_conv4s<3,64,128,16> <<<dim3(4,4,NB),256>>>(patch, -1, 10, eb1, 0);
  k_conv4s<64,128,64,8> <<<dim3(16,1,NB),256>>>(nullptr, 0, 11, eb2, 1);
  k_conv3s<128,128,8,false,false,true><<<dim3(16,NB),256>>>(1, 12, eb3, 2);
  // residual block 1
  k_conv3s<128,32,8,true,true,false><<<dim3(4,NB),256>>>(2, 13, nullptr, 3);
  k_res1x1v<<<dim3(4,NB),256>>>(3, er1b, 2);
  // residual block 2
  k_conv3s<128,32,8,true,true,false><<<dim3(4,NB),256>>>(2, 14, nullptr, 3);
  k_res1x1v<<<dim3(4,NB),256>>>(3, er2b, 2);
  // pre-quant (relu fused into input)
  k_pqv<<<dim3(4,NB),256>>>(2, pqw, pqb);
  // vector quantization
  k_vq<<<512,128>>>(emb);

  // decoder
  k_conv3s<64,128,8,false,false,true><<<dim3(16,NB),256>>>(5, 17, db1, 6);
  k_conv3s<128,32,8,true,true,false><<<dim3(4,NB),256>>>(6, 15, nullptr, 3);
  k_res1x1v<<<dim3(4,NB),256>>>(3, dr1b, 6);
  k_conv3s<128,32,8,true,true,false><<<dim3(4,NB),256>>>(6, 16, nullptr, 3);
  k_res1x1v<<<dim3(4,NB),256>>>(3, dr2b, 6);
  k_convT2s<<<dim3(4,4,NB),256>>>(db2);
  k_convT3s<<<dim3(2,8,NB),256>>>(db3, out);

  // losses + indices
  k_loss<<<1,512>>>(out);
  k_final<<<256,256>>>(out);
}